// round 11
// baseline (speedup 1.0000x reference)
#include <cuda_runtime.h>
#include <cuda_bf16.h>
#include <math.h>
#include <stdint.h>

#define BATCH 2
#define SEQ   4096
#define DM    1024
#define NH    16
#define DH    64
#define L3    3072
#define ROWS  (BATCH*SEQ)

// ---------------- device scratch (allocation-free) ----------------
__device__ float g_qkv[(size_t)ROWS * L3];
__device__ __nv_bfloat16 g_xh[(size_t)ROWS*DM],  g_xl[(size_t)ROWS*DM];
__device__ __nv_bfloat16 g_wqh[(size_t)DM*L3],   g_wql[(size_t)DM*L3];
__device__ __nv_bfloat16 g_woh[(size_t)DM*DM],   g_wol[(size_t)DM*DM];
__device__ __nv_bfloat16 g_Qh[(size_t)ROWS*DM],  g_Ql[(size_t)ROWS*DM];
__device__ __nv_bfloat16 g_Kh[(size_t)ROWS*DM],  g_Kl[(size_t)ROWS*DM];
__device__ __nv_bfloat16 g_Vh[(size_t)ROWS*DM],  g_Vl[(size_t)ROWS*DM];
__device__ __nv_bfloat16 g_ath[(size_t)ROWS*DM], g_atl[(size_t)ROWS*DM];

// ---------------- helpers ----------------
__device__ __forceinline__ uint32_t pack2(__nv_bfloat16 a, __nv_bfloat16 b) {
    __nv_bfloat162 t; t.x = a; t.y = b;
    return *reinterpret_cast<uint32_t*>(&t);
}
__device__ __forceinline__ void split1(float f, __nv_bfloat16& h, __nv_bfloat16& l) {
    h = __float2bfloat16_rn(f);
    l = __float2bfloat16_rn(f - __bfloat162float(h));
}
__device__ __forceinline__ void split_pack2(float f0, float f1, uint32_t& h, uint32_t& l) {
    __nv_bfloat16 h0, l0, h1, l1;
    split1(f0, h0, l0); split1(f1, h1, l1);
    h = pack2(h0, h1); l = pack2(l0, l1);
}
__device__ __forceinline__ void mma_bf16(float c[4],
                                         uint32_t a0, uint32_t a1, uint32_t a2, uint32_t a3,
                                         uint32_t b0, uint32_t b1) {
    asm volatile(
        "mma.sync.aligned.m16n8k16.row.col.f32.bf16.bf16.f32 "
        "{%0,%1,%2,%3}, {%4,%5,%6,%7}, {%8,%9}, {%0,%1,%2,%3};\n"
        : "+f"(c[0]), "+f"(c[1]), "+f"(c[2]), "+f"(c[3])
        : "r"(a0), "r"(a1), "r"(a2), "r"(a3), "r"(b0), "r"(b1));
}
#define LDSM4(r0,r1,r2,r3,addr) \
    asm volatile("ldmatrix.sync.aligned.m8n8.x4.shared.b16 {%0,%1,%2,%3}, [%4];" \
                 : "=r"(r0),"=r"(r1),"=r"(r2),"=r"(r3) : "r"(addr))
#define CP16(s,g)  asm volatile("cp.async.cg.shared.global [%0], [%1], 16;" :: "r"(s), "l"(g))
#define CPCOMMIT() asm volatile("cp.async.commit_group;" ::: "memory")
#define CPWAIT0()  asm volatile("cp.async.wait_group 0;" ::: "memory")

// ---------------- prep kernels ----------------
__global__ void prep_wT(const float* __restrict__ W,
                        __nv_bfloat16* __restrict__ WTh, __nv_bfloat16* __restrict__ WTl,
                        int K, int N)
{
    __shared__ float t[32][33];
    const int tid = threadIdx.x;
    const int n0 = blockIdx.x * 32, k0 = blockIdx.y * 32;
    #pragma unroll
    for (int i = 0; i < 4; i++) {
        int idx = i * 256 + tid;
        t[idx >> 5][idx & 31] = W[(size_t)(k0 + (idx >> 5)) * N + n0 + (idx & 31)];
    }
    __syncthreads();
    uint32_t* oh = (uint32_t*)WTh;
    uint32_t* ol = (uint32_t*)WTl;
    #pragma unroll
    for (int i = 0; i < 2; i++) {
        int idx = i * 256 + tid;
        int n = idx >> 4, kp = idx & 15;
        uint32_t h, l;
        split_pack2(t[2*kp][n], t[2*kp+1][n], h, l);
        size_t o = ((size_t)(n0 + n) * K + k0) / 2 + kp;
        oh[o] = h; ol[o] = l;
    }
}

__global__ void prep_x(const float* __restrict__ x,
                       __nv_bfloat16* __restrict__ xh, __nv_bfloat16* __restrict__ xl)
{
    size_t i = (size_t)blockIdx.x * 256 + threadIdx.x;
    float2 v = ((const float2*)x)[i];
    uint32_t h, l;
    split_pack2(v.x, v.y, h, l);
    ((uint32_t*)xh)[i] = h;
    ((uint32_t*)xl)[i] = l;
}

__global__ void prep_qkv(const float* __restrict__ qkv)
{
    __shared__ float vs[64][65];
    const int tid = threadIdx.x;
    const int lt = blockIdx.x, h = blockIdx.y, b = blockIdx.z;
    const size_t rowg = (size_t)b * SEQ + lt * 64;
    const size_t bh = (size_t)b * NH + h;

    uint32_t* Qh32 = (uint32_t*)g_Qh; uint32_t* Ql32 = (uint32_t*)g_Ql;
    uint32_t* Kh32 = (uint32_t*)g_Kh; uint32_t* Kl32 = (uint32_t*)g_Kl;
    uint32_t* Vh32 = (uint32_t*)g_Vh; uint32_t* Vl32 = (uint32_t*)g_Vl;

    const float nl = -0.194206455f;   // ln(500)/32
    #pragma unroll
    for (int i = 0; i < 4; i++) {
        int idx = i * 256 + tid;
        int r = idx >> 4, j = idx & 15;
        int l = lt * 64 + r;
        const float* row = qkv + (rowg + r) * L3;
        float f0 = expf((float)(2*j)     * nl);
        float f1 = expf((float)(2*j + 1) * nl);
        float s0, c0, s1, c1;
        sincosf((float)l * f0, &s0, &c0);
        sincosf((float)l * f1, &s1, &c1);
        size_t ob = (bh * SEQ + l) * 32;
        {
            const float* q = row + h * 64;
            float t1a = q[2*j], t1b = q[2*j+1], t2a = q[2*j+32], t2b = q[2*j+33];
            uint32_t hh, ll;
            split_pack2((t1a*c0 - t2a*s0) * 0.125f, (t1b*c1 - t2b*s1) * 0.125f, hh, ll);
            Qh32[ob + j] = hh;      Ql32[ob + j] = ll;
            split_pack2((t1a*s0 + t2a*c0) * 0.125f, (t1b*s1 + t2b*c1) * 0.125f, hh, ll);
            Qh32[ob + 16 + j] = hh; Ql32[ob + 16 + j] = ll;
        }
        {
            const float* k = row + 1024 + h * 64;
            float t1a = k[2*j], t1b = k[2*j+1], t2a = k[2*j+32], t2b = k[2*j+33];
            uint32_t hh, ll;
            split_pack2(t1a*c0 - t2a*s0, t1b*c1 - t2b*s1, hh, ll);
            Kh32[ob + j] = hh;      Kl32[ob + j] = ll;
            split_pack2(t1a*s0 + t2a*c0, t1b*s1 + t2b*c1, hh, ll);
            Kh32[ob + 16 + j] = hh; Kl32[ob + 16 + j] = ll;
        }
    }
    #pragma unroll
    for (int i = 0; i < 4; i++) {
        int idx = i * 256 + tid;
        int r = idx >> 4, c4 = (idx & 15) * 4;
        float4 v = *(const float4*)(qkv + (rowg + r) * L3 + 2048 + h * 64 + c4);
        vs[r][c4] = v.x; vs[r][c4+1] = v.y; vs[r][c4+2] = v.z; vs[r][c4+3] = v.w;
    }
    __syncthreads();
    #pragma unroll
    for (int i = 0; i < 8; i++) {
        int idx = i * 256 + tid;
        int d = idx >> 5, lp = idx & 31;
        uint32_t hh, ll;
        split_pack2(vs[2*lp][d], vs[2*lp+1][d], hh, ll);
        size_t o = (bh * 64 + d) * (SEQ/2) + lt * 32 + lp;
        Vh32[o] = hh; Vl32[o] = ll;
    }
}

// ---------------------------------------------------------------------------
// Split-bf16 GEMM + bias, mma.sync.  256x128 tile, 512 threads (16 warps).
// BK=64, 2-stage ring -> 16 barriers per K=1024 (half of round-9's 32).
// XOR-swizzled 128B rows (SW128 pattern) -> stage 98304 B, total 196608 B.
// ---------------------------------------------------------------------------
#define GS4_STAGE 98304
#define GS4_SMEM  (2*GS4_STAGE)
#define GA_LO   32768          // Al offset within stage
#define GB_BASE 65536          // Bh offset within stage
#define GB_LO   16384          // Bl offset from GB_BASE
#define SWZ(off, row) ((uint32_t)(off) ^ (((uint32_t)(row) & 7u) << 4))

__global__ __launch_bounds__(512, 1)
void gemm_bf16(const __nv_bfloat16* __restrict__ Ahg, const __nv_bfloat16* __restrict__ Alg,
               const __nv_bfloat16* __restrict__ Bhg, const __nv_bfloat16* __restrict__ Blg,
               const float* __restrict__ bias, float* __restrict__ C,
               int M, int N, int K)
{
    extern __shared__ char smc[];
    const uint32_t smb = (uint32_t)__cvta_generic_to_shared(smc);
    const int tid = threadIdx.x, lane = tid & 31, wid = tid >> 5;
    const int wm = wid & 3, wn = wid >> 2;
    const int m0 = blockIdx.y * 256, n0 = blockIdx.x * 128;
    const int nk = K >> 6;

    // A staging: one full 128B k-row per thread (8 chunks, swizzled)
    const int arow = tid & 255;
    const char* aSrc = (const char*)((tid < 256 ? Ahg : Alg) + (size_t)(m0 + arow) * K);
    const uint32_t aDst = smb + (tid < 256 ? 0 : GA_LO) + arow * 128;
    const uint32_t aswz = ((uint32_t)(arow & 7)) << 4;
    // B staging: half a 128B k-row per thread (4 chunks, swizzled)
    const int brow = (tid & 255) >> 1;
    const int bh64 = tid & 1;
    const char* bSrc = (const char*)((tid < 256 ? Bhg : Blg) + (size_t)(n0 + brow) * K) + bh64 * 64;
    const uint32_t bDst = smb + GB_BASE + (tid < 256 ? 0 : GB_LO) + brow * 128;
    const uint32_t bswz = ((uint32_t)(brow & 7)) << 4;
    const uint32_t bco = (uint32_t)(bh64 * 64);

    #define G4_LOAD(s, kt) do { \
        const char* a_ = aSrc + (size_t)(kt) * 128; \
        const char* b_ = bSrc + (size_t)(kt) * 128; \
        uint32_t ad_ = aDst + (s) * GS4_STAGE, bd_ = bDst + (s) * GS4_STAGE; \
        _Pragma("unroll") \
        for (int q = 0; q < 8; q++) CP16(ad_ + ((uint32_t)(q*16) ^ aswz), a_ + q*16); \
        _Pragma("unroll") \
        for (int q = 0; q < 4; q++) CP16(bd_ + ((bco + q*16) ^ bswz), b_ + q*16); \
    } while (0)

    float acc[4][4][4];
    #pragma unroll
    for (int i = 0; i < 4; i++)
        #pragma unroll
        for (int j = 0; j < 4; j++)
            #pragma unroll
            for (int k = 0; k < 4; k++) acc[i][j][k] = 0.0f;

    const int rowA = ((lane >> 3) & 1) * 8 + (lane & 7);
    const int colA = (lane >> 4) * 16;
    const int rowB = (lane >> 4) * 8 + (lane & 7);
    const int colB = ((lane >> 3) & 1) * 16;

    G4_LOAD(0, 0); CPCOMMIT();

    for (int kt = 0; kt < nk; kt++) {
        CPWAIT0();            // load kt complete (own thread)
        __syncthreads();      // visible to all; prior iter's reads of other stage done
        if (kt + 1 < nk) G4_LOAD((kt + 1) & 1, kt + 1);
        CPCOMMIT();
        const uint32_t st = smb + (uint32_t)(kt & 1) * GS4_STAGE;

        #pragma unroll
        for (int ks = 0; ks < 4; ks++) {
            uint32_t ah[4][4], al_[4][4];
            #pragma unroll
            for (int mt = 0; mt < 4; mt++) {
                uint32_t R = (uint32_t)(wm * 64 + mt * 16 + rowA);
                uint32_t aa = st + R * 128 + SWZ(ks * 32 + colA, R);
                LDSM4(ah[mt][0], ah[mt][1], ah[mt][2], ah[mt][3], aa);
                LDSM4(al_[mt][0], al_[mt][1], al_[mt][2], al_[mt][3], aa + GA_LO);
            }
            #pragma unroll
            for (int ntp = 0; ntp < 2; ntp++) {
                uint32_t R = (uint32_t)(wn * 32 + ntp * 16 + rowB);
                uint32_t ba = st + GB_BASE + R * 128 + SWZ(ks * 32 + colB, R);
                uint32_t bh0, bh1, bh2, bh3, bl0, bl1, bl2, bl3;
                LDSM4(bh0, bh1, bh2, bh3, ba);
                LDSM4(bl0, bl1, bl2, bl3, ba + GB_LO);
                #pragma unroll
                for (int mt = 0; mt < 4; mt++) {
                    mma_bf16(acc[mt][2*ntp],   ah[mt][0], ah[mt][1], ah[mt][2], ah[mt][3], bh0, bh1);
                    mma_bf16(acc[mt][2*ntp+1], ah[mt][0], ah[mt][1], ah[mt][2], ah[mt][3], bh2, bh3);
                }
                #pragma unroll
                for (int mt = 0; mt < 4; mt++) {
                    mma_bf16(acc[mt][2*ntp],   ah[mt][0], ah[mt][1], ah[mt][2], ah[mt][3], bl0, bl1);
                    mma_bf16(acc[mt][2*ntp+1], ah[mt][0], ah[mt][1], ah[mt][2], ah[mt][3], bl2, bl3);
                }
                #pragma unroll
                for (int mt = 0; mt < 4; mt++) {
                    mma_bf16(acc[mt][2*ntp],   al_[mt][0], al_[mt][1], al_[mt][2], al_[mt][3], bh0, bh1);
                    mma_bf16(acc[mt][2*ntp+1], al_[mt][0], al_[mt][1], al_[mt][2], al_[mt][3], bh2, bh3);
                }
            }
        }
    }

    #pragma unroll
    for (int nt = 0; nt < 4; nt++) {
        int col = n0 + wn * 32 + nt * 8 + (lane & 3) * 2;
        float2 bs = *(const float2*)&bias[col];
        #pragma unroll
        for (int mt = 0; mt < 4; mt++) {
            int r = m0 + wm * 64 + mt * 16 + (lane >> 2);
            float2 v0 = { acc[mt][nt][0] + bs.x, acc[mt][nt][1] + bs.y };
            float2 v1 = { acc[mt][nt][2] + bs.x, acc[mt][nt][3] + bs.y };
            *(float2*)&C[(size_t)r * N + col]       = v0;
            *(float2*)&C[(size_t)(r + 8) * N + col] = v1;
        }
    }
}

// ---------------------------------------------------------------------------
// Flash attention (round-9 version, unchanged / known-good)
// ---------------------------------------------------------------------------
#define FQ     36864
#define FSTAGE 36864
#define FSM    (FQ + 2*FSTAGE)

__global__ __launch_bounds__(256, 2)
void flash_bf16(const __nv_bfloat16* __restrict__ Qh, const __nv_bfloat16* __restrict__ Ql,
                const __nv_bfloat16* __restrict__ Kh, const __nv_bfloat16* __restrict__ Kl,
                const __nv_bfloat16* __restrict__ Vh, const __nv_bfloat16* __restrict__ Vl)
{
    extern __shared__ char smc[];
    const uint32_t smb = (uint32_t)__cvta_generic_to_shared(smc);
    const int tid = threadIdx.x, lane = tid & 31, wid = tid >> 5;
    const int qt = blockIdx.x, h = blockIdx.y, b = blockIdx.z;
    const size_t bh = (size_t)b * NH + h;

    {
        const int qtile = tid >> 7;
        const int qr = tid & 127;
        const __nv_bfloat16* qsrc = qtile ? Ql : Qh;
        const char* gq = (const char*)(qsrc + (bh * SEQ + (size_t)qt * 128 + qr) * 64);
        uint32_t sq = smb + qtile * 18432 + qr * 144;
        #pragma unroll
        for (int c = 0; c < 8; c++) CP16(sq + c*16, gq + c*16);
    }
    const int tile = tid >> 6;
    const int krow = tid & 63;
    const char* gkv;
    int gstride;
    if (tile == 0)      { gkv = (const char*)(Kh + (bh * SEQ + krow) * 64); gstride = 8192; }
    else if (tile == 1) { gkv = (const char*)(Kl + (bh * SEQ + krow) * 64); gstride = 8192; }
    else if (tile == 2) { gkv = (const char*)(Vh + (bh * 64 + krow) * SEQ); gstride = 128; }
    else                { gkv = (const char*)(Vl + (bh * 64 + krow) * SEQ); gstride = 128; }
    const uint32_t skv = smb + FQ + tile * 9216 + krow * 144;
    #pragma unroll
    for (int c = 0; c < 8; c++) CP16(skv + c*16, gkv + c*16);
    CPCOMMIT();

    float s[8][4], o[8][4];
    float m0r = -INFINITY, m1r = -INFINITY, l0r = 0.0f, l1r = 0.0f;
    #pragma unroll
    for (int i = 0; i < 8; i++)
        #pragma unroll
        for (int j = 0; j < 4; j++) o[i][j] = 0.0f;

    const int rowA = ((lane >> 3) & 1) * 8 + (lane & 7);
    const int colA = (lane >> 4) * 16;
    const int rowB = (lane >> 4) * 8 + (lane & 7);
    const int colB = ((lane >> 3) & 1) * 16;

    for (int t = 0; t < SEQ / 64; t++) {
        CPWAIT0();
        __syncthreads();
        if (t < SEQ / 64 - 1) {
            const char* gp = gkv + (size_t)(t + 1) * gstride;
            uint32_t sp = skv + ((t + 1) & 1) * FSTAGE;
            #pragma unroll
            for (int c = 0; c < 8; c++) CP16(sp + c*16, gp + c*16);
        }
        CPCOMMIT();
        const uint32_t kvb = smb + FQ + (t & 1) * FSTAGE;

        #pragma unroll
        for (int i = 0; i < 8; i++)
            #pragma unroll
            for (int j = 0; j < 4; j++) s[i][j] = 0.0f;

        #pragma unroll
        for (int ks = 0; ks < 4; ks++) {
            uint32_t qa = smb + (uint32_t)(wid * 16 + rowA) * 144 + ks * 32 + colA;
            uint32_t qh0, qh1, qh2, qh3, ql0, ql1, ql2, ql3;
            LDSM4(qh0, qh1, qh2, qh3, qa);
            LDSM4(ql0, ql1, ql2, ql3, qa + 18432);
            #pragma unroll
            for (int np = 0; np < 2; np++) {
                uint32_t kh[2][4], kl[2][4];
                #pragma unroll
                for (int p = 0; p < 2; p++) {
                    uint32_t ka = kvb + (uint32_t)((np*2+p) * 16 + rowB) * 144 + ks * 32 + colB;
                    LDSM4(kh[p][0], kh[p][1], kh[p][2], kh[p][3], ka);
                    LDSM4(kl[p][0], kl[p][1], kl[p][2], kl[p][3], ka + 9216);
                }
                #pragma unroll
                for (int p = 0; p < 2; p++) {
                    mma_bf16(s[2*(np*2+p)],   qh0, qh1, qh2, qh3, kh[p][0], kh[p][1]);
                    mma_bf16(s[2*(np*2+p)+1], qh0, qh1, qh2, qh3, kh[p][2], kh[p][3]);
                }
                #pragma unroll
                for (int p = 0; p < 2; p++) {
                    mma_bf16(s[2*(np*2+p)],   qh0, qh1, qh2, qh3, kl[p][0], kl[p][1]);
                    mma_bf16(s[2*(np*2+p)+1], qh0, qh1, qh2, qh3, kl[p][2], kl[p][3]);
                }
                #pragma unroll
                for (int p = 0; p < 2; p++) {
                    mma_bf16(s[2*(np*2+p)],   ql0, ql1, ql2, ql3, kh[p][0], kh[p][1]);
                    mma_bf16(s[2*(np*2+p)+1], ql0, ql1, ql2, ql3, kh[p][2], kh[p][3]);
                }
            }
        }

        float mx0 = -INFINITY, mx1 = -INFINITY;
        #pragma unroll
        for (int nt = 0; nt < 8; nt++) {
            mx0 = fmaxf(mx0, fmaxf(s[nt][0], s[nt][1]));
            mx1 = fmaxf(mx1, fmaxf(s[nt][2], s[nt][3]));
        }
        mx0 = fmaxf(mx0, __shfl_xor_sync(0xffffffffu, mx0, 1));
        mx0 = fmaxf(mx0, __shfl_xor_sync(0xffffffffu, mx0, 2));
        mx1 = fmaxf(mx1, __shfl_xor_sync(0xffffffffu, mx1, 1));
        mx1 = fmaxf(mx1, __shfl_xor_sync(0xffffffffu, mx1, 2));
        float mn0 = fmaxf(m0r, mx0), mn1 = fmaxf(m1r, mx1);
        float a0 = __expf(m0r - mn0), a1 = __expf(m1r - mn1);
        float sum0 = 0.0f, sum1 = 0.0f;
        #pragma unroll
        for (int nt = 0; nt < 8; nt++) {
            s[nt][0] = __expf(s[nt][0] - mn0); sum0 += s[nt][0];
            s[nt][1] = __expf(s[nt][1] - mn0); sum0 += s[nt][1];
            s[nt][2] = __expf(s[nt][2] - mn1); sum1 += s[nt][2];
            s[nt][3] = __expf(s[nt][3] - mn1); sum1 += s[nt][3];
        }
        sum0 += __shfl_xor_sync(0xffffffffu, sum0, 1);
        sum0 += __shfl_xor_sync(0xffffffffu, sum0, 2);
        sum1 += __shfl_xor_sync(0xffffffffu, sum1, 1);
        sum1 += __shfl_xor_sync(0xffffffffu, sum1, 2);
        l0r = l0r * a0 + sum0;  l1r = l1r * a1 + sum1;
        m0r = mn0;              m1r = mn1;
        #pragma unroll
        for (int dt = 0; dt < 8; dt++) {
            o[dt][0] *= a0; o[dt][1] *= a0;
            o[dt][2] *= a1; o[dt][3] *= a1;
        }

        #pragma unroll
        for (int kt = 0; kt < 4; kt++) {
            uint32_t ah0, ah1, ah2, ah3, au0, au1, au2, au3;
            split_pack2(s[2*kt][0],   s[2*kt][1],   ah0, au0);
            split_pack2(s[2*kt][2],   s[2*kt][3],   ah1, au1);
            split_pack2(s[2*kt+1][0], s[2*kt+1][1], ah2, au2);
            split_pack2(s[2*kt+1][2], s[2*kt+1][3], ah3, au3);
            #pragma unroll
            for (int dp = 0; dp < 2; dp++) {
                uint32_t vh[2][4], vl[2][4];
                #pragma unroll
                for (int p = 0; p < 2; p++) {
                    uint32_t va = kvb + 18432 + (uint32_t)((dp*2+p) * 16 + rowB) * 144 + kt * 32 + colB;
                    LDSM4(vh[p][0], vh[p][1], vh[p][2], vh[p][3], va);
                    LDSM4(vl[p][0], vl[p][1], vl[p][2], vl[p][3], va + 9216);
                }
                #pragma unroll
                for (int p = 0; p < 2; p++) {
                    mma_bf16(o[2*(dp*2+p)],   ah0, ah1, ah2, ah3, vh[p][0], vh[p][1]);
                    mma_bf16(o[2*(dp*2+p)+1], ah0, ah1, ah2, ah3, vh[p][2], vh[p][3]);
                }
                #pragma unroll
                for (int p = 0; p < 2; p++) {
                    mma_bf16(o[2*(dp*2+p)],   ah0, ah1, ah2, ah3, vl[p][0], vl[p][1]);
                    mma_bf16(o[2*(dp*2+p)+1], ah0, ah1, ah2, ah3, vl[p][2], vl[p][3]);
                }
                #pragma unroll
                for (int p = 0; p < 2; p++) {
                    mma_bf16(o[2*(dp*2+p)],   au0, au1, au2, au3, vh[p][0], vh[p][1]);
                    mma_bf16(o[2*(dp*2+p)+1], au0, au1, au2, au3, vh[p][2], vh[p][3]);
                }
            }
        }
    }

    float inv0 = 1.0f / l0r, inv1 = 1.0f / l1r;
    const size_t row = (size_t)b * SEQ + (size_t)qt * 128 + wid * 16 + (lane >> 2);
    uint32_t* oh32 = (uint32_t*)g_ath;
    uint32_t* ol32 = (uint32_t*)g_atl;
    #pragma unroll
    for (int dt = 0; dt < 8; dt++) {
        int cp = h * 32 + dt * 4 + (lane & 3);
        uint32_t hh, ll;
        split_pack2(o[dt][0] * inv0, o[dt][1] * inv0, hh, ll);
        oh32[row * 512 + cp] = hh;       ol32[row * 512 + cp] = ll;
        split_pack2(o[dt][2] * inv1, o[dt][3] * inv1, hh, ll);
        oh32[(row + 8) * 512 + cp] = hh; ol32[(row + 8) * 512 + cp] = ll;
    }
}

// ---------------------------------------------------------------------------
// Launcher
// ---------------------------------------------------------------------------
extern "C" void kernel_launch(void* const* d_in, const int* in_sizes, int n_in,
                              void* d_out, int out_size)
{
    const float* x     = (const float*)d_in[0];
    const float* w_qkv = (const float*)d_in[1];
    const float* b_qkv = (const float*)d_in[2];
    const float* w_out = (const float*)d_in[3];
    const float* b_out = (const float*)d_in[4];
    float* out = (float*)d_out;

    float* qkvp;
    __nv_bfloat16 *xh, *xl, *wqh, *wql, *woh, *wol, *Qh, *Ql, *Kh, *Kl, *Vh, *Vl, *ath, *atl;
    cudaGetSymbolAddress((void**)&qkvp, g_qkv);
    cudaGetSymbolAddress((void**)&xh, g_xh);   cudaGetSymbolAddress((void**)&xl, g_xl);
    cudaGetSymbolAddress((void**)&wqh, g_wqh); cudaGetSymbolAddress((void**)&wql, g_wql);
    cudaGetSymbolAddress((void**)&woh, g_woh); cudaGetSymbolAddress((void**)&wol, g_wol);
    cudaGetSymbolAddress((void**)&Qh, g_Qh);   cudaGetSymbolAddress((void**)&Ql, g_Ql);
    cudaGetSymbolAddress((void**)&Kh, g_Kh);   cudaGetSymbolAddress((void**)&Kl, g_Kl);
    cudaGetSymbolAddress((void**)&Vh, g_Vh);   cudaGetSymbolAddress((void**)&Vl, g_Vl);
    cudaGetSymbolAddress((void**)&ath, g_ath); cudaGetSymbolAddress((void**)&atl, g_atl);

    cudaFuncSetAttribute(gemm_bf16,  cudaFuncAttributeMaxDynamicSharedMemorySize, GS4_SMEM);
    cudaFuncSetAttribute(flash_bf16, cudaFuncAttributeMaxDynamicSharedMemorySize, FSM);

    prep_wT<<<dim3(L3 / 32, DM / 32), 256>>>(w_qkv, wqh, wql, DM, L3);
    prep_wT<<<dim3(DM / 32, DM / 32), 256>>>(w_out, woh, wol, DM, DM);
    prep_x<<<(int)(((size_t)ROWS * DM / 2) / 256), 256>>>(x, xh, xl);

    gemm_bf16<<<dim3(L3 / 128, ROWS / 256), 512, GS4_SMEM>>>(xh, xl, wqh, wql, b_qkv, qkvp,
                                                             ROWS, L3, DM);
    prep_qkv<<<dim3(SEQ / 64, NH, BATCH), 256>>>(qkvp);

    flash_bf16<<<dim3(SEQ / 128, NH, BATCH), 256, FSM>>>(Qh, Ql, Kh, Kl, Vh, Vl);

    gemm_bf16<<<dim3(DM / 128, ROWS / 256), 512, GS4_SMEM>>>(ath, atl, woh, wol, b_out, out,
                                                             ROWS, DM, DM);
}

// round 12
// speedup vs baseline: 1.4464x; 1.4464x over previous
#include <cuda_runtime.h>
#include <cuda_fp16.h>
#include <math.h>
#include <stdint.h>

#define BATCH 2
#define SEQ   4096
#define DM    1024
#define NH    16
#define DH    64
#define L3    3072
#define ROWS  (BATCH*SEQ)

// ---------------- device scratch (allocation-free) ----------------
__device__ float g_qkv[(size_t)ROWS * L3];
__device__ __half g_xh[(size_t)ROWS*DM],  g_xl[(size_t)ROWS*DM];
__device__ __half g_wqh[(size_t)DM*L3];            // w_qkv^T [3072][1024] fp16 (single)
__device__ __half g_woh[(size_t)DM*DM];            // w_out^T fp16 (single)
__device__ __half g_Qh[(size_t)ROWS*DM], g_Ql[(size_t)ROWS*DM];  // Q split, pre-scaled 1/8
__device__ __half g_Kh[(size_t)ROWS*DM];           // K single fp16
__device__ __half g_Vh[(size_t)ROWS*DM];           // V single fp16, [b][h][d][SEQ]
__device__ __half g_ath[(size_t)ROWS*DM], g_atl[(size_t)ROWS*DM]; // attention out split

// ---------------- helpers ----------------
__device__ __forceinline__ uint32_t pack2h(__half a, __half b) {
    __half2 t; t.x = a; t.y = b;
    return *reinterpret_cast<uint32_t*>(&t);
}
__device__ __forceinline__ void split1h(float f, __half& h, __half& l) {
    h = __float2half_rn(f);
    l = __float2half_rn(f - __half2float(h));
}
__device__ __forceinline__ void split_pack2h(float f0, float f1, uint32_t& h, uint32_t& l) {
    __half h0, l0, h1, l1;
    split1h(f0, h0, l0); split1h(f1, h1, l1);
    h = pack2h(h0, h1); l = pack2h(l0, l1);
}
__device__ __forceinline__ void mma_f16(float c[4],
                                        uint32_t a0, uint32_t a1, uint32_t a2, uint32_t a3,
                                        uint32_t b0, uint32_t b1) {
    asm volatile(
        "mma.sync.aligned.m16n8k16.row.col.f32.f16.f16.f32 "
        "{%0,%1,%2,%3}, {%4,%5,%6,%7}, {%8,%9}, {%0,%1,%2,%3};\n"
        : "+f"(c[0]), "+f"(c[1]), "+f"(c[2]), "+f"(c[3])
        : "r"(a0), "r"(a1), "r"(a2), "r"(a3), "r"(b0), "r"(b1));
}
#define LDSM4(r0,r1,r2,r3,addr) \
    asm volatile("ldmatrix.sync.aligned.m8n8.x4.shared.b16 {%0,%1,%2,%3}, [%4];" \
                 : "=r"(r0),"=r"(r1),"=r"(r2),"=r"(r3) : "r"(addr))
#define CP16(s,g)  asm volatile("cp.async.cg.shared.global [%0], [%1], 16;" :: "r"(s), "l"(g))
#define CPCOMMIT() asm volatile("cp.async.commit_group;" ::: "memory")
#define CPWAIT1()  asm volatile("cp.async.wait_group 1;" ::: "memory")
#define CPWAIT0()  asm volatile("cp.async.wait_group 0;" ::: "memory")

// ---------------- prep kernels ----------------
// transpose + fp16 round (single): W[K][N] f32 -> WT[N][K] fp16
__global__ void prep_wT(const float* __restrict__ W, __half* __restrict__ WTh,
                        int K, int N)
{
    __shared__ float t[32][33];
    const int tid = threadIdx.x;
    const int n0 = blockIdx.x * 32, k0 = blockIdx.y * 32;
    #pragma unroll
    for (int i = 0; i < 4; i++) {
        int idx = i * 256 + tid;
        t[idx >> 5][idx & 31] = W[(size_t)(k0 + (idx >> 5)) * N + n0 + (idx & 31)];
    }
    __syncthreads();
    uint32_t* oh = (uint32_t*)WTh;
    #pragma unroll
    for (int i = 0; i < 2; i++) {
        int idx = i * 256 + tid;
        int n = idx >> 4, kp = idx & 15;
        uint32_t h = pack2h(__float2half_rn(t[2*kp][n]), __float2half_rn(t[2*kp+1][n]));
        oh[((size_t)(n0 + n) * K + k0) / 2 + kp] = h;
    }
}

__global__ void prep_x(const float* __restrict__ x,
                       __half* __restrict__ xh, __half* __restrict__ xl)
{
    size_t i = (size_t)blockIdx.x * 256 + threadIdx.x;
    float2 v = ((const float2*)x)[i];
    uint32_t h, l;
    split_pack2h(v.x, v.y, h, l);
    ((uint32_t*)xh)[i] = h;
    ((uint32_t*)xl)[i] = l;
}

__global__ void prep_qkv(const float* __restrict__ qkv)
{
    __shared__ float vs[64][65];
    const int tid = threadIdx.x;
    const int lt = blockIdx.x, h = blockIdx.y, b = blockIdx.z;
    const size_t rowg = (size_t)b * SEQ + lt * 64;
    const size_t bh = (size_t)b * NH + h;

    uint32_t* Qh32 = (uint32_t*)g_Qh; uint32_t* Ql32 = (uint32_t*)g_Ql;
    uint32_t* Kh32 = (uint32_t*)g_Kh;
    uint32_t* Vh32 = (uint32_t*)g_Vh;

    const float nl = -0.194206455f;   // -ln(500)/32
    #pragma unroll
    for (int i = 0; i < 4; i++) {
        int idx = i * 256 + tid;
        int r = idx >> 4, j = idx & 15;
        int l = lt * 64 + r;
        const float* row = qkv + (rowg + r) * L3;
        float f0 = expf((float)(2*j)     * nl);
        float f1 = expf((float)(2*j + 1) * nl);
        float s0, c0, s1, c1;
        sincosf((float)l * f0, &s0, &c0);
        sincosf((float)l * f1, &s1, &c1);
        size_t ob = (bh * SEQ + l) * 32;
        {
            const float* q = row + h * 64;
            float t1a = q[2*j], t1b = q[2*j+1], t2a = q[2*j+32], t2b = q[2*j+33];
            uint32_t hh, ll;
            split_pack2h((t1a*c0 - t2a*s0) * 0.125f, (t1b*c1 - t2b*s1) * 0.125f, hh, ll);
            Qh32[ob + j] = hh;      Ql32[ob + j] = ll;
            split_pack2h((t1a*s0 + t2a*c0) * 0.125f, (t1b*s1 + t2b*c1) * 0.125f, hh, ll);
            Qh32[ob + 16 + j] = hh; Ql32[ob + 16 + j] = ll;
        }
        {
            const float* k = row + 1024 + h * 64;
            float t1a = k[2*j], t1b = k[2*j+1], t2a = k[2*j+32], t2b = k[2*j+33];
            Kh32[ob + j] = pack2h(__float2half_rn(t1a*c0 - t2a*s0),
                                  __float2half_rn(t1b*c1 - t2b*s1));
            Kh32[ob + 16 + j] = pack2h(__float2half_rn(t1a*s0 + t2a*c0),
                                       __float2half_rn(t1b*s1 + t2b*c1));
        }
    }
    #pragma unroll
    for (int i = 0; i < 4; i++) {
        int idx = i * 256 + tid;
        int r = idx >> 4, c4 = (idx & 15) * 4;
        float4 v = *(const float4*)(qkv + (rowg + r) * L3 + 2048 + h * 64 + c4);
        vs[r][c4] = v.x; vs[r][c4+1] = v.y; vs[r][c4+2] = v.z; vs[r][c4+3] = v.w;
    }
    __syncthreads();
    #pragma unroll
    for (int i = 0; i < 8; i++) {
        int idx = i * 256 + tid;
        int d = idx >> 5, lp = idx & 31;
        uint32_t hh = pack2h(__float2half_rn(vs[2*lp][d]), __float2half_rn(vs[2*lp+1][d]));
        Vh32[(bh * 64 + d) * (SEQ/2) + lt * 32 + lp] = hh;
    }
}

// ---------------------------------------------------------------------------
// fp16 2-term GEMM + bias: C = (Ah+Al) @ Bh^T + bias.  2 MMAs per product.
// CTA 256x128, 512 threads (16 warps, 4m x 4n), BK=32, 3-stage cp.async ring.
// Stage (51200 B): Ah[256x80] Al[256x80] Bh[128x80], rows 80 B padded.
// ---------------------------------------------------------------------------
#define GS5_STAGE 51200
#define GS5_SMEM  (3*GS5_STAGE)
#define G5_AL 20480
#define G5_B  40960

__global__ __launch_bounds__(512, 1)
void gemm_f16(const __half* __restrict__ Ahg, const __half* __restrict__ Alg,
              const __half* __restrict__ Bhg,
              const float* __restrict__ bias, float* __restrict__ C,
              int M, int N, int K)
{
    extern __shared__ char smc[];
    const uint32_t smb = (uint32_t)__cvta_generic_to_shared(smc);
    const int tid = threadIdx.x, lane = tid & 31, wid = tid >> 5;
    const int wm = wid & 3, wn = wid >> 2;
    const int m0 = blockIdx.y * 256, n0 = blockIdx.x * 128;
    const int nk = K >> 5;

    const int arow = tid & 255;
    const char* aSrc = (const char*)((tid < 256 ? Ahg : Alg) + (size_t)(m0 + arow) * K);
    const uint32_t aDst = smb + (tid < 256 ? 0 : G5_AL) + arow * 80;
    const bool doB = (tid < 128);
    const char* bSrc = doB ? (const char*)(Bhg + (size_t)(n0 + tid) * K) : (const char*)Bhg;
    const uint32_t bDst = smb + G5_B + (tid & 127) * 80;

    #define G5_LOAD(s, kt) do { \
        const char* a_ = aSrc + (size_t)(kt) * 64; \
        uint32_t ad_ = aDst + (s) * GS5_STAGE; \
        CP16(ad_,      a_);       CP16(ad_ + 16, a_ + 16); \
        CP16(ad_ + 32, a_ + 32);  CP16(ad_ + 48, a_ + 48); \
        if (doB) { \
            const char* b_ = bSrc + (size_t)(kt) * 64; \
            uint32_t bd_ = bDst + (s) * GS5_STAGE; \
            CP16(bd_,      b_);       CP16(bd_ + 16, b_ + 16); \
            CP16(bd_ + 32, b_ + 32);  CP16(bd_ + 48, b_ + 48); \
        } \
    } while (0)

    float acc[4][4][4];
    #pragma unroll
    for (int i = 0; i < 4; i++)
        #pragma unroll
        for (int j = 0; j < 4; j++)
            #pragma unroll
            for (int k = 0; k < 4; k++) acc[i][j][k] = 0.0f;

    const int rowA = ((lane >> 3) & 1) * 8 + (lane & 7);
    const int colA = (lane >> 4) * 16;
    const int rowB = (lane >> 4) * 8 + (lane & 7);
    const int colB = ((lane >> 3) & 1) * 16;

    G5_LOAD(0, 0); CPCOMMIT();
    G5_LOAD(1, 1); CPCOMMIT();

    for (int kt = 0; kt < nk; kt++) {
        CPWAIT1();
        __syncthreads();
        if (kt + 2 < nk) G5_LOAD((kt + 2) % 3, kt + 2);
        CPCOMMIT();
        const uint32_t st = smb + (uint32_t)(kt % 3) * GS5_STAGE;

        #pragma unroll
        for (int ks = 0; ks < 2; ks++) {
            uint32_t ah[4][4], al_[4][4];
            #pragma unroll
            for (int mt = 0; mt < 4; mt++) {
                uint32_t aa = st + (uint32_t)(wm * 64 + mt * 16 + rowA) * 80 + ks * 32 + colA;
                LDSM4(ah[mt][0], ah[mt][1], ah[mt][2], ah[mt][3], aa);
                LDSM4(al_[mt][0], al_[mt][1], al_[mt][2], al_[mt][3], aa + G5_AL);
            }
            #pragma unroll
            for (int ntp = 0; ntp < 2; ntp++) {
                uint32_t ba = st + G5_B + (uint32_t)(wn * 32 + ntp * 16 + rowB) * 80 + ks * 32 + colB;
                uint32_t bh0, bh1, bh2, bh3;
                LDSM4(bh0, bh1, bh2, bh3, ba);
                #pragma unroll
                for (int mt = 0; mt < 4; mt++) {
                    mma_f16(acc[mt][2*ntp],   ah[mt][0], ah[mt][1], ah[mt][2], ah[mt][3], bh0, bh1);
                    mma_f16(acc[mt][2*ntp+1], ah[mt][0], ah[mt][1], ah[mt][2], ah[mt][3], bh2, bh3);
                }
                #pragma unroll
                for (int mt = 0; mt < 4; mt++) {
                    mma_f16(acc[mt][2*ntp],   al_[mt][0], al_[mt][1], al_[mt][2], al_[mt][3], bh0, bh1);
                    mma_f16(acc[mt][2*ntp+1], al_[mt][0], al_[mt][1], al_[mt][2], al_[mt][3], bh2, bh3);
                }
            }
        }
    }

    #pragma unroll
    for (int nt = 0; nt < 4; nt++) {
        int col = n0 + wn * 32 + nt * 8 + (lane & 3) * 2;
        float2 bs = *(const float2*)&bias[col];
        #pragma unroll
        for (int mt = 0; mt < 4; mt++) {
            int r = m0 + wm * 64 + mt * 16 + (lane >> 2);
            float2 v0 = { acc[mt][nt][0] + bs.x, acc[mt][nt][1] + bs.y };
            float2 v1 = { acc[mt][nt][2] + bs.x, acc[mt][nt][3] + bs.y };
            *(float2*)&C[(size_t)r * N + col]       = v0;
            *(float2*)&C[(size_t)(r + 8) * N + col] = v1;
        }
    }
}

// ---------------------------------------------------------------------------
// Flash attention, fp16 2-term: S = (Qh+Ql)·Kh^T, O += (Ph+Pl)·Vh.
// 128 MMAs/iter (vs 192).  Q split in smem; K,V single fp16, 2-stage ring.
// smem: Qh(18432) Ql(18432) | 2 x { Kh(9216) Vh(9216) } = 110592 B.
// ---------------------------------------------------------------------------
#define FQ     36864
#define FSTAGE 18432
#define FSM    (FQ + 2*FSTAGE)

__global__ __launch_bounds__(256, 2)
void flash_f16(const __half* __restrict__ Qh, const __half* __restrict__ Ql,
               const __half* __restrict__ Kh, const __half* __restrict__ Vh)
{
    extern __shared__ char smc[];
    const uint32_t smb = (uint32_t)__cvta_generic_to_shared(smc);
    const int tid = threadIdx.x, lane = tid & 31, wid = tid >> 5;
    const int qt = blockIdx.x, h = blockIdx.y, b = blockIdx.z;
    const size_t bh = (size_t)b * NH + h;

    // Q staging: hi/lo by tid>>7, one 128B row per thread
    {
        const int qtile = tid >> 7;
        const int qr = tid & 127;
        const __half* qsrc = qtile ? Ql : Qh;
        const char* gq = (const char*)(qsrc + (bh * SEQ + (size_t)qt * 128 + qr) * 64);
        uint32_t sq = smb + qtile * 18432 + qr * 144;
        #pragma unroll
        for (int c = 0; c < 8; c++) CP16(sq + c*16, gq + c*16);
    }
    // K/V staging: tile = tid>>7 (0=K, 1=V), each thread loads half a row (64B)
    const int tile = tid >> 7;
    const int krow = (tid & 127) >> 1;
    const int khalf = tid & 1;
    const char* gkv;
    int gstride;
    if (tile == 0) { gkv = (const char*)(Kh + (bh * SEQ + krow) * 64) + khalf * 64; gstride = 8192; }
    else           { gkv = (const char*)(Vh + (bh * 64 + krow) * SEQ) + khalf * 64; gstride = 128; }
    const uint32_t skv = smb + FQ + tile * 9216 + krow * 144 + khalf * 64;
    #pragma unroll
    for (int c = 0; c < 4; c++) CP16(skv + c*16, gkv + c*16);
    CPCOMMIT();

    float s[8][4], o[8][4];
    float m0r = -INFINITY, m1r = -INFINITY, l0r = 0.0f, l1r = 0.0f;
    #pragma unroll
    for (int i = 0; i < 8; i++)
        #pragma unroll
        for (int j = 0; j < 4; j++) o[i][j] = 0.0f;

    const int rowA = ((lane >> 3) & 1) * 8 + (lane & 7);
    const int colA = (lane >> 4) * 16;
    const int rowB = (lane >> 4) * 8 + (lane & 7);
    const int colB = ((lane >> 3) & 1) * 16;

    for (int t = 0; t < SEQ / 64; t++) {
        CPWAIT0();
        __syncthreads();
        if (t < SEQ / 64 - 1) {
            const char* gp = gkv + (size_t)(t + 1) * gstride;
            uint32_t sp = skv + ((t + 1) & 1) * FSTAGE;
            #pragma unroll
            for (int c = 0; c < 4; c++) CP16(sp + c*16, gp + c*16);
        }
        CPCOMMIT();
        const uint32_t kvb = smb + FQ + (t & 1) * FSTAGE;

        #pragma unroll
        for (int i = 0; i < 8; i++)
            #pragma unroll
            for (int j = 0; j < 4; j++) s[i][j] = 0.0f;

        // ---- S = (Qh+Ql) @ Kh^T : 2 MMAs per (ks, ntp-half)
        #pragma unroll
        for (int ks = 0; ks < 4; ks++) {
            uint32_t qa = smb + (uint32_t)(wid * 16 + rowA) * 144 + ks * 32 + colA;
            uint32_t qh0, qh1, qh2, qh3, ql0, ql1, ql2, ql3;
            LDSM4(qh0, qh1, qh2, qh3, qa);
            LDSM4(ql0, ql1, ql2, ql3, qa + 18432);
            #pragma unroll
            for (int ntp = 0; ntp < 4; ntp++) {
                uint32_t ka = kvb + (uint32_t)(ntp * 16 + rowB) * 144 + ks * 32 + colB;
                uint32_t kh0, kh1, kh2, kh3;
                LDSM4(kh0, kh1, kh2, kh3, ka);
                mma_f16(s[2*ntp],   qh0, qh1, qh2, qh3, kh0, kh1);
                mma_f16(s[2*ntp+1], qh0, qh1, qh2, qh3, kh2, kh3);
                mma_f16(s[2*ntp],   ql0, ql1, ql2, ql3, kh0, kh1);
                mma_f16(s[2*ntp+1], ql0, ql1, ql2, ql3, kh2, kh3);
            }
        }

        // ---- online softmax
        float mx0 = -INFINITY, mx1 = -INFINITY;
        #pragma unroll
        for (int nt = 0; nt < 8; nt++) {
            mx0 = fmaxf(mx0, fmaxf(s[nt][0], s[nt][1]));
            mx1 = fmaxf(mx1, fmaxf(s[nt][2], s[nt][3]));
        }
        mx0 = fmaxf(mx0, __shfl_xor_sync(0xffffffffu, mx0, 1));
        mx0 = fmaxf(mx0, __shfl_xor_sync(0xffffffffu, mx0, 2));
        mx1 = fmaxf(mx1, __shfl_xor_sync(0xffffffffu, mx1, 1));
        mx1 = fmaxf(mx1, __shfl_xor_sync(0xffffffffu, mx1, 2));
        float mn0 = fmaxf(m0r, mx0), mn1 = fmaxf(m1r, mx1);
        float a0 = __expf(m0r - mn0), a1 = __expf(m1r - mn1);
        float sum0 = 0.0f, sum1 = 0.0f;
        #pragma unroll
        for (int nt = 0; nt < 8; nt++) {
            s[nt][0] = __expf(s[nt][0] - mn0); sum0 += s[nt][0];
            s[nt][1] = __expf(s[nt][1] - mn0); sum0 += s[nt][1];
            s[nt][2] = __expf(s[nt][2] - mn1); sum1 += s[nt][2];
            s[nt][3] = __expf(s[nt][3] - mn1); sum1 += s[nt][3];
        }
        sum0 += __shfl_xor_sync(0xffffffffu, sum0, 1);
        sum0 += __shfl_xor_sync(0xffffffffu, sum0, 2);
        sum1 += __shfl_xor_sync(0xffffffffu, sum1, 1);
        sum1 += __shfl_xor_sync(0xffffffffu, sum1, 2);
        l0r = l0r * a0 + sum0;  l1r = l1r * a1 + sum1;
        m0r = mn0;              m1r = mn1;
        #pragma unroll
        for (int dt = 0; dt < 8; dt++) {
            o[dt][0] *= a0; o[dt][1] *= a0;
            o[dt][2] *= a1; o[dt][3] *= a1;
        }

        // ---- O += (Ph+Pl) @ Vh : register split of P, 2 MMAs per (kt, dtp-half)
        #pragma unroll
        for (int kt = 0; kt < 4; kt++) {
            uint32_t ah0, ah1, ah2, ah3, au0, au1, au2, au3;
            split_pack2h(s[2*kt][0],   s[2*kt][1],   ah0, au0);
            split_pack2h(s[2*kt][2],   s[2*kt][3],   ah1, au1);
            split_pack2h(s[2*kt+1][0], s[2*kt+1][1], ah2, au2);
            split_pack2h(s[2*kt+1][2], s[2*kt+1][3], ah3, au3);
            #pragma unroll
            for (int dtp = 0; dtp < 4; dtp++) {
                uint32_t va = kvb + 9216 + (uint32_t)(dtp * 16 + rowB) * 144 + kt * 32 + colB;
                uint32_t vh0, vh1, vh2, vh3;
                LDSM4(vh0, vh1, vh2, vh3, va);
                mma_f16(o[2*dtp],   ah0, ah1, ah2, ah3, vh0, vh1);
                mma_f16(o[2*dtp+1], ah0, ah1, ah2, ah3, vh2, vh3);
                mma_f16(o[2*dtp],   au0, au1, au2, au3, vh0, vh1);
                mma_f16(o[2*dtp+1], au0, au1, au2, au3, vh2, vh3);
            }
        }
    }

    // epilogue: normalize, split fp16 h/l for the out-proj A-side
    float inv0 = 1.0f / l0r, inv1 = 1.0f / l1r;
    const size_t row = (size_t)b * SEQ + (size_t)qt * 128 + wid * 16 + (lane >> 2);
    uint32_t* oh32 = (uint32_t*)g_ath;
    uint32_t* ol32 = (uint32_t*)g_atl;
    #pragma unroll
    for (int dt = 0; dt < 8; dt++) {
        int cp = h * 32 + dt * 4 + (lane & 3);
        uint32_t hh, ll;
        split_pack2h(o[dt][0] * inv0, o[dt][1] * inv0, hh, ll);
        oh32[row * 512 + cp] = hh;       ol32[row * 512 + cp] = ll;
        split_pack2h(o[dt][2] * inv1, o[dt][3] * inv1, hh, ll);
        oh32[(row + 8) * 512 + cp] = hh; ol32[(row + 8) * 512 + cp] = ll;
    }
}

// ---------------------------------------------------------------------------
// Launcher
// ---------------------------------------------------------------------------
extern "C" void kernel_launch(void* const* d_in, const int* in_sizes, int n_in,
                              void* d_out, int out_size)
{
    const float* x     = (const float*)d_in[0];
    const float* w_qkv = (const float*)d_in[1];
    const float* b_qkv = (const float*)d_in[2];
    const float* w_out = (const float*)d_in[3];
    const float* b_out = (const float*)d_in[4];
    float* out = (float*)d_out;

    float* qkvp;
    __half *xh, *xl, *wqh, *woh, *Qh, *Ql, *Kh, *Vh, *ath, *atl;
    cudaGetSymbolAddress((void**)&qkvp, g_qkv);
    cudaGetSymbolAddress((void**)&xh, g_xh);   cudaGetSymbolAddress((void**)&xl, g_xl);
    cudaGetSymbolAddress((void**)&wqh, g_wqh);
    cudaGetSymbolAddress((void**)&woh, g_woh);
    cudaGetSymbolAddress((void**)&Qh, g_Qh);   cudaGetSymbolAddress((void**)&Ql, g_Ql);
    cudaGetSymbolAddress((void**)&Kh, g_Kh);
    cudaGetSymbolAddress((void**)&Vh, g_Vh);
    cudaGetSymbolAddress((void**)&ath, g_ath); cudaGetSymbolAddress((void**)&atl, g_atl);

    cudaFuncSetAttribute(gemm_f16,  cudaFuncAttributeMaxDynamicSharedMemorySize, GS5_SMEM);
    cudaFuncSetAttribute(flash_f16, cudaFuncAttributeMaxDynamicSharedMemorySize, FSM);

    prep_wT<<<dim3(L3 / 32, DM / 32), 256>>>(w_qkv, wqh, DM, L3);
    prep_wT<<<dim3(DM / 32, DM / 32), 256>>>(w_out, woh, DM, DM);
    prep_x<<<(int)(((size_t)ROWS * DM / 2) / 256), 256>>>(x, xh, xl);

    // QKV projection
    gemm_f16<<<dim3(L3 / 128, ROWS / 256), 512, GS5_SMEM>>>(xh, xl, wqh, b_qkv, qkvp,
                                                            ROWS, L3, DM);
    // RoPE + fp16 conversion
    prep_qkv<<<dim3(SEQ / 64, NH, BATCH), 256>>>(qkvp);

    // flash attention
    flash_f16<<<dim3(SEQ / 128, NH, BATCH), 256, FSM>>>(Qh, Ql, Kh, Vh);

    // output projection
    gemm_f16<<<dim3(DM / 128, ROWS / 256), 512, GS5_SMEM>>>(ath, atl, woh, b_out, out,
                                                            ROWS, DM, DM);
}

// round 14
// speedup vs baseline: 1.5600x; 1.0785x over previous
#include <cuda_runtime.h>
#include <cuda_fp16.h>
#include <math.h>
#include <stdint.h>

#define BATCH 2
#define SEQ   4096
#define DM    1024
#define NH    16
#define DH    64
#define L3    3072
#define ROWS  (BATCH*SEQ)

// ---------------- device scratch (allocation-free) ----------------
__device__ float g_qkv[(size_t)ROWS * L3];
__device__ __half g_xh[(size_t)ROWS*DM],  g_xl[(size_t)ROWS*DM];
__device__ __half g_wqh[(size_t)DM*L3];
__device__ __half g_woh[(size_t)DM*DM];
__device__ __half g_Qh[(size_t)ROWS*DM], g_Ql[(size_t)ROWS*DM];
__device__ __half g_Kh[(size_t)ROWS*DM];
__device__ __half g_Vh[(size_t)ROWS*DM];
__device__ __half g_ath[(size_t)ROWS*DM], g_atl[(size_t)ROWS*DM];

// ---------------- helpers ----------------
__device__ __forceinline__ uint32_t pack2h(__half a, __half b) {
    __half2 t; t.x = a; t.y = b;
    return *reinterpret_cast<uint32_t*>(&t);
}
__device__ __forceinline__ void split1h(float f, __half& h, __half& l) {
    h = __float2half_rn(f);
    l = __float2half_rn(f - __half2float(h));
}
__device__ __forceinline__ void split_pack2h(float f0, float f1, uint32_t& h, uint32_t& l) {
    __half h0, l0, h1, l1;
    split1h(f0, h0, l0); split1h(f1, h1, l1);
    h = pack2h(h0, h1); l = pack2h(l0, l1);
}
__device__ __forceinline__ void mma_f16(float c[4],
                                        uint32_t a0, uint32_t a1, uint32_t a2, uint32_t a3,
                                        uint32_t b0, uint32_t b1) {
    asm volatile(
        "mma.sync.aligned.m16n8k16.row.col.f32.f16.f16.f32 "
        "{%0,%1,%2,%3}, {%4,%5,%6,%7}, {%8,%9}, {%0,%1,%2,%3};\n"
        : "+f"(c[0]), "+f"(c[1]), "+f"(c[2]), "+f"(c[3])
        : "r"(a0), "r"(a1), "r"(a2), "r"(a3), "r"(b0), "r"(b1));
}
#define LDSM4(r0,r1,r2,r3,addr) \
    asm volatile("ldmatrix.sync.aligned.m8n8.x4.shared.b16 {%0,%1,%2,%3}, [%4];" \
                 : "=r"(r0),"=r"(r1),"=r"(r2),"=r"(r3) : "r"(addr))
#define CP16(s,g)  asm volatile("cp.async.cg.shared.global [%0], [%1], 16;" :: "r"(s), "l"(g))
#define CPCOMMIT() asm volatile("cp.async.commit_group;" ::: "memory")
#define CPWAIT1()  asm volatile("cp.async.wait_group 1;" ::: "memory")
#define CPWAIT0()  asm volatile("cp.async.wait_group 0;" ::: "memory")

// ---------------- prep kernels ----------------
__global__ void prep_wT(const float* __restrict__ W, __half* __restrict__ WTh,
                        int K, int N)
{
    __shared__ float t[32][33];
    const int tid = threadIdx.x;
    const int n0 = blockIdx.x * 32, k0 = blockIdx.y * 32;
    #pragma unroll
    for (int i = 0; i < 4; i++) {
        int idx = i * 256 + tid;
        t[idx >> 5][idx & 31] = W[(size_t)(k0 + (idx >> 5)) * N + n0 + (idx & 31)];
    }
    __syncthreads();
    uint32_t* oh = (uint32_t*)WTh;
    #pragma unroll
    for (int i = 0; i < 2; i++) {
        int idx = i * 256 + tid;
        int n = idx >> 4, kp = idx & 15;
        uint32_t h = pack2h(__float2half_rn(t[2*kp][n]), __float2half_rn(t[2*kp+1][n]));
        oh[((size_t)(n0 + n) * K + k0) / 2 + kp] = h;
    }
}

__global__ void prep_x(const float* __restrict__ x,
                       __half* __restrict__ xh, __half* __restrict__ xl)
{
    size_t i = (size_t)blockIdx.x * 256 + threadIdx.x;
    float2 v = ((const float2*)x)[i];
    uint32_t h, l;
    split_pack2h(v.x, v.y, h, l);
    ((uint32_t*)xh)[i] = h;
    ((uint32_t*)xl)[i] = l;
}

__global__ void prep_qkv(const float* __restrict__ qkv)
{
    __shared__ float vs[64][65];
    const int tid = threadIdx.x;
    const int lt = blockIdx.x, h = blockIdx.y, b = blockIdx.z;
    const size_t rowg = (size_t)b * SEQ + lt * 64;
    const size_t bh = (size_t)b * NH + h;

    uint32_t* Qh32 = (uint32_t*)g_Qh; uint32_t* Ql32 = (uint32_t*)g_Ql;
    uint32_t* Kh32 = (uint32_t*)g_Kh;
    uint32_t* Vh32 = (uint32_t*)g_Vh;

    const float nl = -0.194206455f;   // -ln(500)/32
    #pragma unroll
    for (int i = 0; i < 4; i++) {
        int idx = i * 256 + tid;
        int r = idx >> 4, j = idx & 15;
        int l = lt * 64 + r;
        const float* row = qkv + (rowg + r) * L3;
        float f0 = expf((float)(2*j)     * nl);
        float f1 = expf((float)(2*j + 1) * nl);
        float s0, c0, s1, c1;
        sincosf((float)l * f0, &s0, &c0);
        sincosf((float)l * f1, &s1, &c1);
        size_t ob = (bh * SEQ + l) * 32;
        {
            const float* q = row + h * 64;
            float t1a = q[2*j], t1b = q[2*j+1], t2a = q[2*j+32], t2b = q[2*j+33];
            uint32_t hh, ll;
            split_pack2h((t1a*c0 - t2a*s0) * 0.125f, (t1b*c1 - t2b*s1) * 0.125f, hh, ll);
            Qh32[ob + j] = hh;      Ql32[ob + j] = ll;
            split_pack2h((t1a*s0 + t2a*c0) * 0.125f, (t1b*s1 + t2b*c1) * 0.125f, hh, ll);
            Qh32[ob + 16 + j] = hh; Ql32[ob + 16 + j] = ll;
        }
        {
            const float* k = row + 1024 + h * 64;
            float t1a = k[2*j], t1b = k[2*j+1], t2a = k[2*j+32], t2b = k[2*j+33];
            Kh32[ob + j] = pack2h(__float2half_rn(t1a*c0 - t2a*s0),
                                  __float2half_rn(t1b*c1 - t2b*s1));
            Kh32[ob + 16 + j] = pack2h(__float2half_rn(t1a*s0 + t2a*c0),
                                       __float2half_rn(t1b*s1 + t2b*c1));
        }
    }
    #pragma unroll
    for (int i = 0; i < 4; i++) {
        int idx = i * 256 + tid;
        int r = idx >> 4, c4 = (idx & 15) * 4;
        float4 v = *(const float4*)(qkv + (rowg + r) * L3 + 2048 + h * 64 + c4);
        vs[r][c4] = v.x; vs[r][c4+1] = v.y; vs[r][c4+2] = v.z; vs[r][c4+3] = v.w;
    }
    __syncthreads();
    #pragma unroll
    for (int i = 0; i < 8; i++) {
        int idx = i * 256 + tid;
        int d = idx >> 5, lp = idx & 31;
        Vh32[(bh * 64 + d) * (SEQ/2) + lt * 32 + lp] =
            pack2h(__float2half_rn(vs[2*lp][d]), __float2half_rn(vs[2*lp+1][d]));
    }
}

// ---------------------------------------------------------------------------
// fp16 2-term GEMM + bias: C = (Ah+Al) @ Bh^T + bias.
// CTA 128x128, 256 threads, 8 warps = 4m x 2n, warp tile 32x64:
// per ks, 8 LDSM4 feed 32 MMAs.  3-stage BK=32 ring, 2 CTAs/SM.
// ---------------------------------------------------------------------------
#define GS6_STAGE 30720
#define GS6_SMEM  (3*GS6_STAGE)
#define G6_AL 10240
#define G6_B  20480

__global__ __launch_bounds__(256, 2)
void gemm_f16(const __half* __restrict__ Ahg, const __half* __restrict__ Alg,
              const __half* __restrict__ Bhg,
              const float* __restrict__ bias, float* __restrict__ C,
              int M, int N, int K)
{
    extern __shared__ char smc[];
    const uint32_t smb = (uint32_t)__cvta_generic_to_shared(smc);
    const int tid = threadIdx.x, lane = tid & 31, wid = tid >> 5;
    const int wm = wid & 3, wn = wid >> 2;
    const int m0 = blockIdx.y * 128, n0 = blockIdx.x * 128;
    const int nk = K >> 5;

    const int arow = tid & 127;
    const char* aSrc = (const char*)((tid < 128 ? Ahg : Alg) + (size_t)(m0 + arow) * K);
    const uint32_t aDst = smb + (tid < 128 ? 0 : G6_AL) + arow * 80;
    const int brow = tid >> 1;
    const int bhalf = tid & 1;
    const char* bSrc = (const char*)(Bhg + (size_t)(n0 + brow) * K) + bhalf * 32;
    const uint32_t bDst = smb + G6_B + brow * 80 + bhalf * 32;

    #define G6_LOAD(s, kt) do { \
        const char* a_ = aSrc + (size_t)(kt) * 64; \
        const char* b_ = bSrc + (size_t)(kt) * 64; \
        uint32_t ad_ = aDst + (s) * GS6_STAGE, bd_ = bDst + (s) * GS6_STAGE; \
        CP16(ad_,      a_);       CP16(ad_ + 16, a_ + 16); \
        CP16(ad_ + 32, a_ + 32);  CP16(ad_ + 48, a_ + 48); \
        CP16(bd_,      b_);       CP16(bd_ + 16, b_ + 16); \
    } while (0)

    float acc[2][8][4];
    #pragma unroll
    for (int i = 0; i < 2; i++)
        #pragma unroll
        for (int j = 0; j < 8; j++)
            #pragma unroll
            for (int k = 0; k < 4; k++) acc[i][j][k] = 0.0f;

    const int rowA = ((lane >> 3) & 1) * 8 + (lane & 7);
    const int colA = (lane >> 4) * 16;
    const int rowB = (lane >> 4) * 8 + (lane & 7);
    const int colB = ((lane >> 3) & 1) * 16;

    G6_LOAD(0, 0); CPCOMMIT();
    G6_LOAD(1, 1); CPCOMMIT();

    for (int kt = 0; kt < nk; kt++) {
        CPWAIT1();
        __syncthreads();
        if (kt + 2 < nk) G6_LOAD((kt + 2) % 3, kt + 2);
        CPCOMMIT();
        const uint32_t st = smb + (uint32_t)(kt % 3) * GS6_STAGE;

        #pragma unroll
        for (int ks = 0; ks < 2; ks++) {
            uint32_t ah[2][4], al_[2][4];
            #pragma unroll
            for (int mt = 0; mt < 2; mt++) {
                uint32_t aa = st + (uint32_t)(wm * 32 + mt * 16 + rowA) * 80 + ks * 32 + colA;
                LDSM4(ah[mt][0], ah[mt][1], ah[mt][2], ah[mt][3], aa);
                LDSM4(al_[mt][0], al_[mt][1], al_[mt][2], al_[mt][3], aa + G6_AL);
            }
            uint32_t bf[4][4];
            #pragma unroll
            for (int ntp = 0; ntp < 4; ntp++) {
                uint32_t ba = st + G6_B + (uint32_t)(wn * 64 + ntp * 16 + rowB) * 80 + ks * 32 + colB;
                LDSM4(bf[ntp][0], bf[ntp][1], bf[ntp][2], bf[ntp][3], ba);
            }
            #pragma unroll
            for (int mt = 0; mt < 2; mt++)
                #pragma unroll
                for (int ntp = 0; ntp < 4; ntp++) {
                    mma_f16(acc[mt][2*ntp],   ah[mt][0], ah[mt][1], ah[mt][2], ah[mt][3],
                            bf[ntp][0], bf[ntp][1]);
                    mma_f16(acc[mt][2*ntp+1], ah[mt][0], ah[mt][1], ah[mt][2], ah[mt][3],
                            bf[ntp][2], bf[ntp][3]);
                }
            #pragma unroll
            for (int mt = 0; mt < 2; mt++)
                #pragma unroll
                for (int ntp = 0; ntp < 4; ntp++) {
                    mma_f16(acc[mt][2*ntp],   al_[mt][0], al_[mt][1], al_[mt][2], al_[mt][3],
                            bf[ntp][0], bf[ntp][1]);
                    mma_f16(acc[mt][2*ntp+1], al_[mt][0], al_[mt][1], al_[mt][2], al_[mt][3],
                            bf[ntp][2], bf[ntp][3]);
                }
        }
    }

    #pragma unroll
    for (int nt = 0; nt < 8; nt++) {
        int col = n0 + wn * 64 + nt * 8 + (lane & 3) * 2;
        float2 bs = *(const float2*)&bias[col];
        #pragma unroll
        for (int mt = 0; mt < 2; mt++) {
            int r = m0 + wm * 32 + mt * 16 + (lane >> 2);
            float2 v0 = { acc[mt][nt][0] + bs.x, acc[mt][nt][1] + bs.y };
            float2 v1 = { acc[mt][nt][2] + bs.x, acc[mt][nt][3] + bs.y };
            *(float2*)&C[(size_t)r * N + col]       = v0;
            *(float2*)&C[(size_t)(r + 8) * N + col] = v1;
        }
    }
}

// ---------------------------------------------------------------------------
// Flash attention (round-12 version, unchanged / known-good)
// ---------------------------------------------------------------------------
#define FQ     36864
#define FSTAGE 18432
#define FSM    (FQ + 2*FSTAGE)

__global__ __launch_bounds__(256, 2)
void flash_f16(const __half* __restrict__ Qh, const __half* __restrict__ Ql,
               const __half* __restrict__ Kh, const __half* __restrict__ Vh)
{
    extern __shared__ char smc[];
    const uint32_t smb = (uint32_t)__cvta_generic_to_shared(smc);
    const int tid = threadIdx.x, lane = tid & 31, wid = tid >> 5;
    const int qt = blockIdx.x, h = blockIdx.y, b = blockIdx.z;
    const size_t bh = (size_t)b * NH + h;

    {
        const int qtile = tid >> 7;
        const int qr = tid & 127;
        const __half* qsrc = qtile ? Ql : Qh;
        const char* gq = (const char*)(qsrc + (bh * SEQ + (size_t)qt * 128 + qr) * 64);
        uint32_t sq = smb + qtile * 18432 + qr * 144;
        #pragma unroll
        for (int c = 0; c < 8; c++) CP16(sq + c*16, gq + c*16);
    }
    const int tile = tid >> 7;
    const int krow = (tid & 127) >> 1;
    const int khalf = tid & 1;
    const char* gkv;
    int gstride;
    if (tile == 0) { gkv = (const char*)(Kh + (bh * SEQ + krow) * 64) + khalf * 64; gstride = 8192; }
    else           { gkv = (const char*)(Vh + (bh * 64 + krow) * SEQ) + khalf * 64; gstride = 128; }
    const uint32_t skv = smb + FQ + tile * 9216 + krow * 144 + khalf * 64;
    #pragma unroll
    for (int c = 0; c < 4; c++) CP16(skv + c*16, gkv + c*16);
    CPCOMMIT();

    float s[8][4], o[8][4];
    float m0r = -INFINITY, m1r = -INFINITY, l0r = 0.0f, l1r = 0.0f;
    #pragma unroll
    for (int i = 0; i < 8; i++)
        #pragma unroll
        for (int j = 0; j < 4; j++) o[i][j] = 0.0f;

    const int rowA = ((lane >> 3) & 1) * 8 + (lane & 7);
    const int colA = (lane >> 4) * 16;
    const int rowB = (lane >> 4) * 8 + (lane & 7);
    const int colB = ((lane >> 3) & 1) * 16;

    for (int t = 0; t < SEQ / 64; t++) {
        CPWAIT0();
        __syncthreads();
        if (t < SEQ / 64 - 1) {
            const char* gp = gkv + (size_t)(t + 1) * gstride;
            uint32_t sp = skv + ((t + 1) & 1) * FSTAGE;
            #pragma unroll
            for (int c = 0; c < 4; c++) CP16(sp + c*16, gp + c*16);
        }
        CPCOMMIT();
        const uint32_t kvb = smb + FQ + (t & 1) * FSTAGE;

        #pragma unroll
        for (int i = 0; i < 8; i++)
            #pragma unroll
            for (int j = 0; j < 4; j++) s[i][j] = 0.0f;

        #pragma unroll
        for (int ks = 0; ks < 4; ks++) {
            uint32_t qa = smb + (uint32_t)(wid * 16 + rowA) * 144 + ks * 32 + colA;
            uint32_t qh0, qh1, qh2, qh3, ql0, ql1, ql2, ql3;
            LDSM4(qh0, qh1, qh2, qh3, qa);
            LDSM4(ql0, ql1, ql2, ql3, qa + 18432);
            #pragma unroll
            for (int ntp = 0; ntp < 4; ntp++) {
                uint32_t ka = kvb + (uint32_t)(ntp * 16 + rowB) * 144 + ks * 32 + colB;
                uint32_t kh0, kh1, kh2, kh3;
                LDSM4(kh0, kh1, kh2, kh3, ka);
                mma_f16(s[2*ntp],   qh0, qh1, qh2, qh3, kh0, kh1);
                mma_f16(s[2*ntp+1], qh0, qh1, qh2, qh3, kh2, kh3);
                mma_f16(s[2*ntp],   ql0, ql1, ql2, ql3, kh0, kh1);
                mma_f16(s[2*ntp+1], ql0, ql1, ql2, ql3, kh2, kh3);
            }
        }

        float mx0 = -INFINITY, mx1 = -INFINITY;
        #pragma unroll
        for (int nt = 0; nt < 8; nt++) {
            mx0 = fmaxf(mx0, fmaxf(s[nt][0], s[nt][1]));
            mx1 = fmaxf(mx1, fmaxf(s[nt][2], s[nt][3]));
        }
        mx0 = fmaxf(mx0, __shfl_xor_sync(0xffffffffu, mx0, 1));
        mx0 = fmaxf(mx0, __shfl_xor_sync(0xffffffffu, mx0, 2));
        mx1 = fmaxf(mx1, __shfl_xor_sync(0xffffffffu, mx1, 1));
        mx1 = fmaxf(mx1, __shfl_xor_sync(0xffffffffu, mx1, 2));
        float mn0 = fmaxf(m0r, mx0), mn1 = fmaxf(m1r, mx1);
        float a0 = __expf(m0r - mn0), a1 = __expf(m1r - mn1);
        float sum0 = 0.0f, sum1 = 0.0f;
        #pragma unroll
        for (int nt = 0; nt < 8; nt++) {
            s[nt][0] = __expf(s[nt][0] - mn0); sum0 += s[nt][0];
            s[nt][1] = __expf(s[nt][1] - mn0); sum0 += s[nt][1];
            s[nt][2] = __expf(s[nt][2] - mn1); sum1 += s[nt][2];
            s[nt][3] = __expf(s[nt][3] - mn1); sum1 += s[nt][3];
        }
        sum0 += __shfl_xor_sync(0xffffffffu, sum0, 1);
        sum0 += __shfl_xor_sync(0xffffffffu, sum0, 2);
        sum1 += __shfl_xor_sync(0xffffffffu, sum1, 1);
        sum1 += __shfl_xor_sync(0xffffffffu, sum1, 2);
        l0r = l0r * a0 + sum0;  l1r = l1r * a1 + sum1;
        m0r = mn0;              m1r = mn1;
        #pragma unroll
        for (int dt = 0; dt < 8; dt++) {
            o[dt][0] *= a0; o[dt][1] *= a0;
            o[dt][2] *= a1; o[dt][3] *= a1;
        }

        #pragma unroll
        for (int kt = 0; kt < 4; kt++) {
            uint32_t ah0, ah1, ah2, ah3, au0, au1, au2, au3;
            split_pack2h(s[2*kt][0],   s[2*kt][1],   ah0, au0);
            split_pack2h(s[2*kt][2],   s[2*kt][3],   ah1, au1);
            split_pack2h(s[2*kt+1][0], s[2*kt+1][1], ah2, au2);
            split_pack2h(s[2*kt+1][2], s[2*kt+1][3], ah3, au3);
            #pragma unroll
            for (int dtp = 0; dtp < 4; dtp++) {
                uint32_t va = kvb + 9216 + (uint32_t)(dtp * 16 + rowB) * 144 + kt * 32 + colB;
                uint32_t vh0, vh1, vh2, vh3;
                LDSM4(vh0, vh1, vh2, vh3, va);
                mma_f16(o[2*dtp],   ah0, ah1, ah2, ah3, vh0, vh1);
                mma_f16(o[2*dtp+1], ah0, ah1, ah2, ah3, vh2, vh3);
                mma_f16(o[2*dtp],   au0, au1, au2, au3, vh0, vh1);
                mma_f16(o[2*dtp+1], au0, au1, au2, au3, vh2, vh3);
            }
        }
    }

    float inv0 = 1.0f / l0r, inv1 = 1.0f / l1r;
    const size_t row = (size_t)b * SEQ + (size_t)qt * 128 + wid * 16 + (lane >> 2);
    uint32_t* oh32 = (uint32_t*)g_ath;
    uint32_t* ol32 = (uint32_t*)g_atl;
    #pragma unroll
    for (int dt = 0; dt < 8; dt++) {
        int cp = h * 32 + dt * 4 + (lane & 3);
        uint32_t hh, ll;
        split_pack2h(o[dt][0] * inv0, o[dt][1] * inv0, hh, ll);
        oh32[row * 512 + cp] = hh;       ol32[row * 512 + cp] = ll;
        split_pack2h(o[dt][2] * inv1, o[dt][3] * inv1, hh, ll);
        oh32[(row + 8) * 512 + cp] = hh; ol32[(row + 8) * 512 + cp] = ll;
    }
}

// ---------------------------------------------------------------------------
// Launcher
// ---------------------------------------------------------------------------
extern "C" void kernel_launch(void* const* d_in, const int* in_sizes, int n_in,
                              void* d_out, int out_size)
{
    const float* x     = (const float*)d_in[0];
    const float* w_qkv = (const float*)d_in[1];
    const float* b_qkv = (const float*)d_in[2];
    const float* w_out = (const float*)d_in[3];
    const float* b_out = (const float*)d_in[4];
    float* out = (float*)d_out;

    float* qkvp;
    __half *xh, *xl, *wqh, *woh, *Qh, *Ql, *Kh, *Vh, *ath, *atl;
    cudaGetSymbolAddress((void**)&qkvp, g_qkv);
    cudaGetSymbolAddress((void**)&xh, g_xh);   cudaGetSymbolAddress((void**)&xl, g_xl);
    cudaGetSymbolAddress((void**)&wqh, g_wqh);
    cudaGetSymbolAddress((void**)&woh, g_woh);
    cudaGetSymbolAddress((void**)&Qh, g_Qh);   cudaGetSymbolAddress((void**)&Ql, g_Ql);
    cudaGetSymbolAddress((void**)&Kh, g_Kh);
    cudaGetSymbolAddress((void**)&Vh, g_Vh);
    cudaGetSymbolAddress((void**)&ath, g_ath); cudaGetSymbolAddress((void**)&atl, g_atl);

    cudaFuncSetAttribute(gemm_f16,  cudaFuncAttributeMaxDynamicSharedMemorySize, GS6_SMEM);
    cudaFuncSetAttribute(flash_f16, cudaFuncAttributeMaxDynamicSharedMemorySize, FSM);

    prep_wT<<<dim3(L3 / 32, DM / 32), 256>>>(w_qkv, wqh, DM, L3);
    prep_wT<<<dim3(DM / 32, DM / 32), 256>>>(w_out, woh, DM, DM);
    prep_x<<<(int)(((size_t)ROWS * DM / 2) / 256), 256>>>(x, xh, xl);

    // QKV projection
    gemm_f16<<<dim3(L3 / 128, ROWS / 128), 256, GS6_SMEM>>>(xh, xl, wqh, b_qkv, qkvp,
                                                            ROWS, L3, DM);
    // RoPE + fp16 conversion
    prep_qkv<<<dim3(SEQ / 64, NH, BATCH), 256>>>(qkvp);

    // flash attention
    flash_f16<<<dim3(SEQ / 128, NH, BATCH), 256, FSM>>>(Qh, Ql, Kh, Vh);

    // output projection
    gemm_f16<<<dim3(DM / 128, ROWS / 128), 256, GS6_SMEM>>>(ath, atl, woh, b_out, out,
                                                            ROWS, DM, DM);
}

// round 15
// speedup vs baseline: 1.6980x; 1.0885x over previous
#include <cuda_runtime.h>
#include <cuda_fp16.h>
#include <math.h>
#include <stdint.h>

#define BATCH 2
#define SEQ   4096
#define DM    1024
#define NH    16
#define DH    64
#define L3    3072
#define ROWS  (BATCH*SEQ)

// ---------------- device scratch (allocation-free) ----------------
__device__ float g_qkv[(size_t)ROWS * L3];
__device__ __half g_xh[(size_t)ROWS*DM],  g_xl[(size_t)ROWS*DM];
__device__ __half g_wqh[(size_t)DM*L3];
__device__ __half g_woh[(size_t)DM*DM];
__device__ __half g_Qh[(size_t)ROWS*DM];           // Q single fp16, pre-scaled 1/8
__device__ __half g_Kh[(size_t)ROWS*DM];           // K single fp16
__device__ __half g_Vh[(size_t)ROWS*DM];           // V single fp16, [b][h][d][SEQ]
__device__ __half g_ath[(size_t)ROWS*DM], g_atl[(size_t)ROWS*DM];

// ---------------- helpers ----------------
__device__ __forceinline__ uint32_t pack2h(__half a, __half b) {
    __half2 t; t.x = a; t.y = b;
    return *reinterpret_cast<uint32_t*>(&t);
}
__device__ __forceinline__ void split1h(float f, __half& h, __half& l) {
    h = __float2half_rn(f);
    l = __float2half_rn(f - __half2float(h));
}
__device__ __forceinline__ void split_pack2h(float f0, float f1, uint32_t& h, uint32_t& l) {
    __half h0, l0, h1, l1;
    split1h(f0, h0, l0); split1h(f1, h1, l1);
    h = pack2h(h0, h1); l = pack2h(l0, l1);
}
__device__ __forceinline__ void mma_f16(float c[4],
                                        uint32_t a0, uint32_t a1, uint32_t a2, uint32_t a3,
                                        uint32_t b0, uint32_t b1) {
    asm volatile(
        "mma.sync.aligned.m16n8k16.row.col.f32.f16.f16.f32 "
        "{%0,%1,%2,%3}, {%4,%5,%6,%7}, {%8,%9}, {%0,%1,%2,%3};\n"
        : "+f"(c[0]), "+f"(c[1]), "+f"(c[2]), "+f"(c[3])
        : "r"(a0), "r"(a1), "r"(a2), "r"(a3), "r"(b0), "r"(b1));
}
#define LDSM4(r0,r1,r2,r3,addr) \
    asm volatile("ldmatrix.sync.aligned.m8n8.x4.shared.b16 {%0,%1,%2,%3}, [%4];" \
                 : "=r"(r0),"=r"(r1),"=r"(r2),"=r"(r3) : "r"(addr))
#define CP16(s,g)  asm volatile("cp.async.cg.shared.global [%0], [%1], 16;" :: "r"(s), "l"(g))
#define CPCOMMIT() asm volatile("cp.async.commit_group;" ::: "memory")
#define CPWAIT1()  asm volatile("cp.async.wait_group 1;" ::: "memory")
#define CPWAIT0()  asm volatile("cp.async.wait_group 0;" ::: "memory")

// ---------------- prep kernels ----------------
__global__ void prep_wT(const float* __restrict__ W, __half* __restrict__ WTh,
                        int K, int N)
{
    __shared__ float t[32][33];
    const int tid = threadIdx.x;
    const int n0 = blockIdx.x * 32, k0 = blockIdx.y * 32;
    #pragma unroll
    for (int i = 0; i < 4; i++) {
        int idx = i * 256 + tid;
        t[idx >> 5][idx & 31] = W[(size_t)(k0 + (idx >> 5)) * N + n0 + (idx & 31)];
    }
    __syncthreads();
    uint32_t* oh = (uint32_t*)WTh;
    #pragma unroll
    for (int i = 0; i < 2; i++) {
        int idx = i * 256 + tid;
        int n = idx >> 4, kp = idx & 15;
        uint32_t h = pack2h(__float2half_rn(t[2*kp][n]), __float2half_rn(t[2*kp+1][n]));
        oh[((size_t)(n0 + n) * K + k0) / 2 + kp] = h;
    }
}

__global__ void prep_x(const float* __restrict__ x,
                       __half* __restrict__ xh, __half* __restrict__ xl)
{
    size_t i = (size_t)blockIdx.x * 256 + threadIdx.x;
    float2 v = ((const float2*)x)[i];
    uint32_t h, l;
    split_pack2h(v.x, v.y, h, l);
    ((uint32_t*)xh)[i] = h;
    ((uint32_t*)xl)[i] = l;
}

__global__ void prep_qkv(const float* __restrict__ qkv)
{
    __shared__ float vs[64][65];
    const int tid = threadIdx.x;
    const int lt = blockIdx.x, h = blockIdx.y, b = blockIdx.z;
    const size_t rowg = (size_t)b * SEQ + lt * 64;
    const size_t bh = (size_t)b * NH + h;

    uint32_t* Qh32 = (uint32_t*)g_Qh;
    uint32_t* Kh32 = (uint32_t*)g_Kh;
    uint32_t* Vh32 = (uint32_t*)g_Vh;

    const float nl = -0.194206455f;   // -ln(500)/32
    #pragma unroll
    for (int i = 0; i < 4; i++) {
        int idx = i * 256 + tid;
        int r = idx >> 4, j = idx & 15;
        int l = lt * 64 + r;
        const float* row = qkv + (rowg + r) * L3;
        float f0 = expf((float)(2*j)     * nl);
        float f1 = expf((float)(2*j + 1) * nl);
        float s0, c0, s1, c1;
        sincosf((float)l * f0, &s0, &c0);
        sincosf((float)l * f1, &s1, &c1);
        size_t ob = (bh * SEQ + l) * 32;
        {
            const float* q = row + h * 64;
            float t1a = q[2*j], t1b = q[2*j+1], t2a = q[2*j+32], t2b = q[2*j+33];
            Qh32[ob + j] = pack2h(__float2half_rn((t1a*c0 - t2a*s0) * 0.125f),
                                  __float2half_rn((t1b*c1 - t2b*s1) * 0.125f));
            Qh32[ob + 16 + j] = pack2h(__float2half_rn((t1a*s0 + t2a*c0) * 0.125f),
                                       __float2half_rn((t1b*s1 + t2b*c1) * 0.125f));
        }
        {
            const float* k = row + 1024 + h * 64;
            float t1a = k[2*j], t1b = k[2*j+1], t2a = k[2*j+32], t2b = k[2*j+33];
            Kh32[ob + j] = pack2h(__float2half_rn(t1a*c0 - t2a*s0),
                                  __float2half_rn(t1b*c1 - t2b*s1));
            Kh32[ob + 16 + j] = pack2h(__float2half_rn(t1a*s0 + t2a*c0),
                                       __float2half_rn(t1b*s1 + t2b*c1));
        }
    }
    #pragma unroll
    for (int i = 0; i < 4; i++) {
        int idx = i * 256 + tid;
        int r = idx >> 4, c4 = (idx & 15) * 4;
        float4 v = *(const float4*)(qkv + (rowg + r) * L3 + 2048 + h * 64 + c4);
        vs[r][c4] = v.x; vs[r][c4+1] = v.y; vs[r][c4+2] = v.z; vs[r][c4+3] = v.w;
    }
    __syncthreads();
    #pragma unroll
    for (int i = 0; i < 8; i++) {
        int idx = i * 256 + tid;
        int d = idx >> 5, lp = idx & 31;
        Vh32[(bh * 64 + d) * (SEQ/2) + lt * 32 + lp] =
            pack2h(__float2half_rn(vs[2*lp][d]), __float2half_rn(vs[2*lp+1][d]));
    }
}

// ---------------------------------------------------------------------------
// fp16 2-term GEMM + bias (round-14 version, unchanged): C = (Ah+Al) @ Bh^T.
// CTA 128x128, 256 threads, 8 warps = 4m x 2n, 3-stage BK=32, 2 CTAs/SM.
// ---------------------------------------------------------------------------
#define GS6_STAGE 30720
#define GS6_SMEM  (3*GS6_STAGE)
#define G6_AL 10240
#define G6_B  20480

__global__ __launch_bounds__(256, 2)
void gemm_f16(const __half* __restrict__ Ahg, const __half* __restrict__ Alg,
              const __half* __restrict__ Bhg,
              const float* __restrict__ bias, float* __restrict__ C,
              int M, int N, int K)
{
    extern __shared__ char smc[];
    const uint32_t smb = (uint32_t)__cvta_generic_to_shared(smc);
    const int tid = threadIdx.x, lane = tid & 31, wid = tid >> 5;
    const int wm = wid & 3, wn = wid >> 2;
    const int m0 = blockIdx.y * 128, n0 = blockIdx.x * 128;
    const int nk = K >> 5;

    const int arow = tid & 127;
    const char* aSrc = (const char*)((tid < 128 ? Ahg : Alg) + (size_t)(m0 + arow) * K);
    const uint32_t aDst = smb + (tid < 128 ? 0 : G6_AL) + arow * 80;
    const int brow = tid >> 1;
    const int bhalf = tid & 1;
    const char* bSrc = (const char*)(Bhg + (size_t)(n0 + brow) * K) + bhalf * 32;
    const uint32_t bDst = smb + G6_B + brow * 80 + bhalf * 32;

    #define G6_LOAD(s, kt) do { \
        const char* a_ = aSrc + (size_t)(kt) * 64; \
        const char* b_ = bSrc + (size_t)(kt) * 64; \
        uint32_t ad_ = aDst + (s) * GS6_STAGE, bd_ = bDst + (s) * GS6_STAGE; \
        CP16(ad_,      a_);       CP16(ad_ + 16, a_ + 16); \
        CP16(ad_ + 32, a_ + 32);  CP16(ad_ + 48, a_ + 48); \
        CP16(bd_,      b_);       CP16(bd_ + 16, b_ + 16); \
    } while (0)

    float acc[2][8][4];
    #pragma unroll
    for (int i = 0; i < 2; i++)
        #pragma unroll
        for (int j = 0; j < 8; j++)
            #pragma unroll
            for (int k = 0; k < 4; k++) acc[i][j][k] = 0.0f;

    const int rowA = ((lane >> 3) & 1) * 8 + (lane & 7);
    const int colA = (lane >> 4) * 16;
    const int rowB = (lane >> 4) * 8 + (lane & 7);
    const int colB = ((lane >> 3) & 1) * 16;

    G6_LOAD(0, 0); CPCOMMIT();
    G6_LOAD(1, 1); CPCOMMIT();

    for (int kt = 0; kt < nk; kt++) {
        CPWAIT1();
        __syncthreads();
        if (kt + 2 < nk) G6_LOAD((kt + 2) % 3, kt + 2);
        CPCOMMIT();
        const uint32_t st = smb + (uint32_t)(kt % 3) * GS6_STAGE;

        #pragma unroll
        for (int ks = 0; ks < 2; ks++) {
            uint32_t ah[2][4], al_[2][4];
            #pragma unroll
            for (int mt = 0; mt < 2; mt++) {
                uint32_t aa = st + (uint32_t)(wm * 32 + mt * 16 + rowA) * 80 + ks * 32 + colA;
                LDSM4(ah[mt][0], ah[mt][1], ah[mt][2], ah[mt][3], aa);
                LDSM4(al_[mt][0], al_[mt][1], al_[mt][2], al_[mt][3], aa + G6_AL);
            }
            uint32_t bf[4][4];
            #pragma unroll
            for (int ntp = 0; ntp < 4; ntp++) {
                uint32_t ba = st + G6_B + (uint32_t)(wn * 64 + ntp * 16 + rowB) * 80 + ks * 32 + colB;
                LDSM4(bf[ntp][0], bf[ntp][1], bf[ntp][2], bf[ntp][3], ba);
            }
            #pragma unroll
            for (int mt = 0; mt < 2; mt++)
                #pragma unroll
                for (int ntp = 0; ntp < 4; ntp++) {
                    mma_f16(acc[mt][2*ntp],   ah[mt][0], ah[mt][1], ah[mt][2], ah[mt][3],
                            bf[ntp][0], bf[ntp][1]);
                    mma_f16(acc[mt][2*ntp+1], ah[mt][0], ah[mt][1], ah[mt][2], ah[mt][3],
                            bf[ntp][2], bf[ntp][3]);
                }
            #pragma unroll
            for (int mt = 0; mt < 2; mt++)
                #pragma unroll
                for (int ntp = 0; ntp < 4; ntp++) {
                    mma_f16(acc[mt][2*ntp],   al_[mt][0], al_[mt][1], al_[mt][2], al_[mt][3],
                            bf[ntp][0], bf[ntp][1]);
                    mma_f16(acc[mt][2*ntp+1], al_[mt][0], al_[mt][1], al_[mt][2], al_[mt][3],
                            bf[ntp][2], bf[ntp][3]);
                }
        }
    }

    #pragma unroll
    for (int nt = 0; nt < 8; nt++) {
        int col = n0 + wn * 64 + nt * 8 + (lane & 3) * 2;
        float2 bs = *(const float2*)&bias[col];
        #pragma unroll
        for (int mt = 0; mt < 2; mt++) {
            int r = m0 + wm * 32 + mt * 16 + (lane >> 2);
            float2 v0 = { acc[mt][nt][0] + bs.x, acc[mt][nt][1] + bs.y };
            float2 v1 = { acc[mt][nt][2] + bs.x, acc[mt][nt][3] + bs.y };
            *(float2*)&C[(size_t)r * N + col]       = v0;
            *(float2*)&C[(size_t)(r + 8) * N + col] = v1;
        }
    }
}

// ---------------------------------------------------------------------------
// Flash attention, Q single fp16: S = Qh·Kh^T (32 MMAs/iter), O += (Ph+Pl)·Vh.
// 96 MMAs/iter (was 128).  smem: Q(18432) | 2 x { Kh(9216) Vh(9216) } = 55296 B.
// ---------------------------------------------------------------------------
#define FQ     18432
#define FSTAGE 18432
#define FSM    (FQ + 2*FSTAGE)

__global__ __launch_bounds__(256, 2)
void flash_f16(const __half* __restrict__ Qh,
               const __half* __restrict__ Kh, const __half* __restrict__ Vh)
{
    extern __shared__ char smc[];
    const uint32_t smb = (uint32_t)__cvta_generic_to_shared(smc);
    const int tid = threadIdx.x, lane = tid & 31, wid = tid >> 5;
    const int qt = blockIdx.x, h = blockIdx.y, b = blockIdx.z;
    const size_t bh = (size_t)b * NH + h;

    // Q staging: 128 rows, each of 256 threads loads half a row (64 B)
    {
        const int qr = tid >> 1;
        const int qhalf = tid & 1;
        const char* gq = (const char*)(Qh + (bh * SEQ + (size_t)qt * 128 + qr) * 64) + qhalf * 64;
        uint32_t sq = smb + qr * 144 + qhalf * 64;
        #pragma unroll
        for (int c = 0; c < 4; c++) CP16(sq + c*16, gq + c*16);
    }
    // K/V staging: tile = tid>>7 (0=K, 1=V), each thread loads half a row (64 B)
    const int tile = tid >> 7;
    const int krow = (tid & 127) >> 1;
    const int khalf = tid & 1;
    const char* gkv;
    int gstride;
    if (tile == 0) { gkv = (const char*)(Kh + (bh * SEQ + krow) * 64) + khalf * 64; gstride = 8192; }
    else           { gkv = (const char*)(Vh + (bh * 64 + krow) * SEQ) + khalf * 64; gstride = 128; }
    const uint32_t skv = smb + FQ + tile * 9216 + krow * 144 + khalf * 64;
    #pragma unroll
    for (int c = 0; c < 4; c++) CP16(skv + c*16, gkv + c*16);
    CPCOMMIT();

    float s[8][4], o[8][4];
    float m0r = -INFINITY, m1r = -INFINITY, l0r = 0.0f, l1r = 0.0f;
    #pragma unroll
    for (int i = 0; i < 8; i++)
        #pragma unroll
        for (int j = 0; j < 4; j++) o[i][j] = 0.0f;

    const int rowA = ((lane >> 3) & 1) * 8 + (lane & 7);
    const int colA = (lane >> 4) * 16;
    const int rowB = (lane >> 4) * 8 + (lane & 7);
    const int colB = ((lane >> 3) & 1) * 16;

    for (int t = 0; t < SEQ / 64; t++) {
        CPWAIT0();
        __syncthreads();
        if (t < SEQ / 64 - 1) {
            const char* gp = gkv + (size_t)(t + 1) * gstride;
            uint32_t sp = skv + ((t + 1) & 1) * FSTAGE;
            #pragma unroll
            for (int c = 0; c < 4; c++) CP16(sp + c*16, gp + c*16);
        }
        CPCOMMIT();
        const uint32_t kvb = smb + FQ + (t & 1) * FSTAGE;

        #pragma unroll
        for (int i = 0; i < 8; i++)
            #pragma unroll
            for (int j = 0; j < 4; j++) s[i][j] = 0.0f;

        // ---- S = Qh @ Kh^T (single-term)
        #pragma unroll
        for (int ks = 0; ks < 4; ks++) {
            uint32_t qa = smb + (uint32_t)(wid * 16 + rowA) * 144 + ks * 32 + colA;
            uint32_t qh0, qh1, qh2, qh3;
            LDSM4(qh0, qh1, qh2, qh3, qa);
            #pragma unroll
            for (int ntp = 0; ntp < 4; ntp++) {
                uint32_t ka = kvb + (uint32_t)(ntp * 16 + rowB) * 144 + ks * 32 + colB;
                uint32_t kh0, kh1, kh2, kh3;
                LDSM4(kh0, kh1, kh2, kh3, ka);
                mma_f16(s[2*ntp],   qh0, qh1, qh2, qh3, kh0, kh1);
                mma_f16(s[2*ntp+1], qh0, qh1, qh2, qh3, kh2, kh3);
            }
        }

        // ---- online softmax
        float mx0 = -INFINITY, mx1 = -INFINITY;
        #pragma unroll
        for (int nt = 0; nt < 8; nt++) {
            mx0 = fmaxf(mx0, fmaxf(s[nt][0], s[nt][1]));
            mx1 = fmaxf(mx1, fmaxf(s[nt][2], s[nt][3]));
        }
        mx0 = fmaxf(mx0, __shfl_xor_sync(0xffffffffu, mx0, 1));
        mx0 = fmaxf(mx0, __shfl_xor_sync(0xffffffffu, mx0, 2));
        mx1 = fmaxf(mx1, __shfl_xor_sync(0xffffffffu, mx1, 1));
        mx1 = fmaxf(mx1, __shfl_xor_sync(0xffffffffu, mx1, 2));
        float mn0 = fmaxf(m0r, mx0), mn1 = fmaxf(m1r, mx1);
        float a0 = __expf(m0r - mn0), a1 = __expf(m1r - mn1);
        float sum0 = 0.0f, sum1 = 0.0f;
        #pragma unroll
        for (int nt = 0; nt < 8; nt++) {
            s[nt][0] = __expf(s[nt][0] - mn0); sum0 += s[nt][0];
            s[nt][1] = __expf(s[nt][1] - mn0); sum0 += s[nt][1];
            s[nt][2] = __expf(s[nt][2] - mn1); sum1 += s[nt][2];
            s[nt][3] = __expf(s[nt][3] - mn1); sum1 += s[nt][3];
        }
        sum0 += __shfl_xor_sync(0xffffffffu, sum0, 1);
        sum0 += __shfl_xor_sync(0xffffffffu, sum0, 2);
        sum1 += __shfl_xor_sync(0xffffffffu, sum1, 1);
        sum1 += __shfl_xor_sync(0xffffffffu, sum1, 2);
        l0r = l0r * a0 + sum0;  l1r = l1r * a1 + sum1;
        m0r = mn0;              m1r = mn1;
        #pragma unroll
        for (int dt = 0; dt < 8; dt++) {
            o[dt][0] *= a0; o[dt][1] *= a0;
            o[dt][2] *= a1; o[dt][3] *= a1;
        }

        // ---- O += (Ph+Pl) @ Vh
        #pragma unroll
        for (int kt = 0; kt < 4; kt++) {
            uint32_t ah0, ah1, ah2, ah3, au0, au1, au2, au3;
            split_pack2h(s[2*kt][0],   s[2*kt][1],   ah0, au0);
            split_pack2h(s[2*kt][2],   s[2*kt][3],   ah1, au1);
            split_pack2h(s[2*kt+1][0], s[2*kt+1][1], ah2, au2);
            split_pack2h(s[2*kt+1][2], s[2*kt+1][3], ah3, au3);
            #pragma unroll
            for (int dtp = 0; dtp < 4; dtp++) {
                uint32_t va = kvb + 9216 + (uint32_t)(dtp * 16 + rowB) * 144 + kt * 32 + colB;
                uint32_t vh0, vh1, vh2, vh3;
                LDSM4(vh0, vh1, vh2, vh3, va);
                mma_f16(o[2*dtp],   ah0, ah1, ah2, ah3, vh0, vh1);
                mma_f16(o[2*dtp+1], ah0, ah1, ah2, ah3, vh2, vh3);
                mma_f16(o[2*dtp],   au0, au1, au2, au3, vh0, vh1);
                mma_f16(o[2*dtp+1], au0, au1, au2, au3, vh2, vh3);
            }
        }
    }

    float inv0 = 1.0f / l0r, inv1 = 1.0f / l1r;
    const size_t row = (size_t)b * SEQ + (size_t)qt * 128 + wid * 16 + (lane >> 2);
    uint32_t* oh32 = (uint32_t*)g_ath;
    uint32_t* ol32 = (uint32_t*)g_atl;
    #pragma unroll
    for (int dt = 0; dt < 8; dt++) {
        int cp = h * 32 + dt * 4 + (lane & 3);
        uint32_t hh, ll;
        split_pack2h(o[dt][0] * inv0, o[dt][1] * inv0, hh, ll);
        oh32[row * 512 + cp] = hh;       ol32[row * 512 + cp] = ll;
        split_pack2h(o[dt][2] * inv1, o[dt][3] * inv1, hh, ll);
        oh32[(row + 8) * 512 + cp] = hh; ol32[(row + 8) * 512 + cp] = ll;
    }
}

// ---------------------------------------------------------------------------
// Launcher
// ---------------------------------------------------------------------------
extern "C" void kernel_launch(void* const* d_in, const int* in_sizes, int n_in,
                              void* d_out, int out_size)
{
    const float* x     = (const float*)d_in[0];
    const float* w_qkv = (const float*)d_in[1];
    const float* b_qkv = (const float*)d_in[2];
    const float* w_out = (const float*)d_in[3];
    const float* b_out = (const float*)d_in[4];
    float* out = (float*)d_out;

    float* qkvp;
    __half *xh, *xl, *wqh, *woh, *Qh, *Kh, *Vh, *ath, *atl;
    cudaGetSymbolAddress((void**)&qkvp, g_qkv);
    cudaGetSymbolAddress((void**)&xh, g_xh);   cudaGetSymbolAddress((void**)&xl, g_xl);
    cudaGetSymbolAddress((void**)&wqh, g_wqh);
    cudaGetSymbolAddress((void**)&woh, g_woh);
    cudaGetSymbolAddress((void**)&Qh, g_Qh);
    cudaGetSymbolAddress((void**)&Kh, g_Kh);
    cudaGetSymbolAddress((void**)&Vh, g_Vh);
    cudaGetSymbolAddress((void**)&ath, g_ath); cudaGetSymbolAddress((void**)&atl, g_atl);

    cudaFuncSetAttribute(gemm_f16,  cudaFuncAttributeMaxDynamicSharedMemorySize, GS6_SMEM);
    cudaFuncSetAttribute(flash_f16, cudaFuncAttributeMaxDynamicSharedMemorySize, FSM);

    prep_wT<<<dim3(L3 / 32, DM / 32), 256>>>(w_qkv, wqh, DM, L3);
    prep_wT<<<dim3(DM / 32, DM / 32), 256>>>(w_out, woh, DM, DM);
    prep_x<<<(int)(((size_t)ROWS * DM / 2) / 256), 256>>>(x, xh, xl);

    // QKV projection
    gemm_f16<<<dim3(L3 / 128, ROWS / 128), 256, GS6_SMEM>>>(xh, xl, wqh, b_qkv, qkvp,
                                                            ROWS, L3, DM);
    // RoPE + fp16 conversion
    prep_qkv<<<dim3(SEQ / 64, NH, BATCH), 256>>>(qkvp);

    // flash attention
    flash_f16<<<dim3(SEQ / 128, NH, BATCH), 256, FSM>>>(Qh, Kh, Vh);

    // output projection
    gemm_f16<<<dim3(DM / 128, ROWS / 128), 256, GS6_SMEM>>>(ath, atl, woh, b_out, out,
                                                            ROWS, DM, DM);
}

// round 16
// speedup vs baseline: 2.0003x; 1.1780x over previous
#include <cuda_runtime.h>
#include <cuda_fp16.h>
#include <math.h>
#include <stdint.h>

#define BATCH 2
#define SEQ   4096
#define DM    1024
#define NH    16
#define DH    64
#define L3    3072
#define ROWS  (BATCH*SEQ)

// ---------------- device scratch (allocation-free) ----------------
__device__ float g_qkv[(size_t)ROWS * L3];
__device__ __half g_xh[(size_t)ROWS*DM];
__device__ __half g_wqh[(size_t)DM*L3];
__device__ __half g_woh[(size_t)DM*DM];
__device__ __half g_Qh[(size_t)ROWS*DM];           // Q single fp16, pre-scaled 1/8
__device__ __half g_Kh[(size_t)ROWS*DM];           // K single fp16
__device__ __half g_Vh[(size_t)ROWS*DM];           // V single fp16, [b][h][d][SEQ]
__device__ __half g_ath[(size_t)ROWS*DM], g_atl[(size_t)ROWS*DM];

// ---------------- helpers ----------------
__device__ __forceinline__ uint32_t pack2h(__half a, __half b) {
    __half2 t; t.x = a; t.y = b;
    return *reinterpret_cast<uint32_t*>(&t);
}
__device__ __forceinline__ void split1h(float f, __half& h, __half& l) {
    h = __float2half_rn(f);
    l = __float2half_rn(f - __half2float(h));
}
__device__ __forceinline__ void split_pack2h(float f0, float f1, uint32_t& h, uint32_t& l) {
    __half h0, l0, h1, l1;
    split1h(f0, h0, l0); split1h(f1, h1, l1);
    h = pack2h(h0, h1); l = pack2h(l0, l1);
}
__device__ __forceinline__ void mma_f16(float c[4],
                                        uint32_t a0, uint32_t a1, uint32_t a2, uint32_t a3,
                                        uint32_t b0, uint32_t b1) {
    asm volatile(
        "mma.sync.aligned.m16n8k16.row.col.f32.f16.f16.f32 "
        "{%0,%1,%2,%3}, {%4,%5,%6,%7}, {%8,%9}, {%0,%1,%2,%3};\n"
        : "+f"(c[0]), "+f"(c[1]), "+f"(c[2]), "+f"(c[3])
        : "r"(a0), "r"(a1), "r"(a2), "r"(a3), "r"(b0), "r"(b1));
}
#define LDSM4(r0,r1,r2,r3,addr) \
    asm volatile("ldmatrix.sync.aligned.m8n8.x4.shared.b16 {%0,%1,%2,%3}, [%4];" \
                 : "=r"(r0),"=r"(r1),"=r"(r2),"=r"(r3) : "r"(addr))
#define CP16(s,g)  asm volatile("cp.async.cg.shared.global [%0], [%1], 16;" :: "r"(s), "l"(g))
#define CPCOMMIT() asm volatile("cp.async.commit_group;" ::: "memory")
#define CPWAIT1()  asm volatile("cp.async.wait_group 1;" ::: "memory")
#define CPWAIT0()  asm volatile("cp.async.wait_group 0;" ::: "memory")

// ---------------- prep kernels ----------------
__global__ void prep_wT(const float* __restrict__ W, __half* __restrict__ WTh,
                        int K, int N)
{
    __shared__ float t[32][33];
    const int tid = threadIdx.x;
    const int n0 = blockIdx.x * 32, k0 = blockIdx.y * 32;
    #pragma unroll
    for (int i = 0; i < 4; i++) {
        int idx = i * 256 + tid;
        t[idx >> 5][idx & 31] = W[(size_t)(k0 + (idx >> 5)) * N + n0 + (idx & 31)];
    }
    __syncthreads();
    uint32_t* oh = (uint32_t*)WTh;
    #pragma unroll
    for (int i = 0; i < 2; i++) {
        int idx = i * 256 + tid;
        int n = idx >> 4, kp = idx & 15;
        uint32_t h = pack2h(__float2half_rn(t[2*kp][n]), __float2half_rn(t[2*kp+1][n]));
        oh[((size_t)(n0 + n) * K + k0) / 2 + kp] = h;
    }
}

__global__ void prep_x(const float* __restrict__ x, __half* __restrict__ xh)
{
    size_t i = (size_t)blockIdx.x * 256 + threadIdx.x;
    float2 v = ((const float2*)x)[i];
    ((uint32_t*)xh)[i] = pack2h(__float2half_rn(v.x), __float2half_rn(v.y));
}

__global__ void prep_qkv(const float* __restrict__ qkv)
{
    __shared__ float vs[64][65];
    const int tid = threadIdx.x;
    const int lt = blockIdx.x, h = blockIdx.y, b = blockIdx.z;
    const size_t rowg = (size_t)b * SEQ + lt * 64;
    const size_t bh = (size_t)b * NH + h;

    uint32_t* Qh32 = (uint32_t*)g_Qh;
    uint32_t* Kh32 = (uint32_t*)g_Kh;
    uint32_t* Vh32 = (uint32_t*)g_Vh;

    const float nl = -0.194206455f;   // -ln(500)/32
    #pragma unroll
    for (int i = 0; i < 4; i++) {
        int idx = i * 256 + tid;
        int r = idx >> 4, j = idx & 15;
        int l = lt * 64 + r;
        const float* row = qkv + (rowg + r) * L3;
        float f0 = expf((float)(2*j)     * nl);
        float f1 = expf((float)(2*j + 1) * nl);
        float s0, c0, s1, c1;
        sincosf((float)l * f0, &s0, &c0);
        sincosf((float)l * f1, &s1, &c1);
        size_t ob = (bh * SEQ + l) * 32;
        {
            const float* q = row + h * 64;
            float t1a = q[2*j], t1b = q[2*j+1], t2a = q[2*j+32], t2b = q[2*j+33];
            Qh32[ob + j] = pack2h(__float2half_rn((t1a*c0 - t2a*s0) * 0.125f),
                                  __float2half_rn((t1b*c1 - t2b*s1) * 0.125f));
            Qh32[ob + 16 + j] = pack2h(__float2half_rn((t1a*s0 + t2a*c0) * 0.125f),
                                       __float2half_rn((t1b*s1 + t2b*c1) * 0.125f));
        }
        {
            const float* k = row + 1024 + h * 64;
            float t1a = k[2*j], t1b = k[2*j+1], t2a = k[2*j+32], t2b = k[2*j+33];
            Kh32[ob + j] = pack2h(__float2half_rn(t1a*c0 - t2a*s0),
                                  __float2half_rn(t1b*c1 - t2b*s1));
            Kh32[ob + 16 + j] = pack2h(__float2half_rn(t1a*s0 + t2a*c0),
                                       __float2half_rn(t1b*s1 + t2b*c1));
        }
    }
    #pragma unroll
    for (int i = 0; i < 4; i++) {
        int idx = i * 256 + tid;
        int r = idx >> 4, c4 = (idx & 15) * 4;
        float4 v = *(const float4*)(qkv + (rowg + r) * L3 + 2048 + h * 64 + c4);
        vs[r][c4] = v.x; vs[r][c4+1] = v.y; vs[r][c4+2] = v.z; vs[r][c4+3] = v.w;
    }
    __syncthreads();
    #pragma unroll
    for (int i = 0; i < 8; i++) {
        int idx = i * 256 + tid;
        int d = idx >> 5, lp = idx & 31;
        Vh32[(bh * 64 + d) * (SEQ/2) + lt * 32 + lp] =
            pack2h(__float2half_rn(vs[2*lp][d]), __float2half_rn(vs[2*lp+1][d]));
    }
}

// ---------------------------------------------------------------------------
// 1-term fp16 GEMM + bias (QKV): C = A @ B^T + bias, A single fp16.
// CTA 128x128, 256 threads, 8 warps = 4m x 2n, 3-stage BK=32, 2 CTAs/SM.
// Stage 20480 B: A[128x80] B[128x80].
// ---------------------------------------------------------------------------
#define G1_STAGE 20480
#define G1_SMEM  (3*G1_STAGE)
#define G1_B     10240

__global__ __launch_bounds__(256, 2)
void gemm_f16_1t(const __half* __restrict__ Ag, const __half* __restrict__ Bg,
                 const float* __restrict__ bias, float* __restrict__ C,
                 int M, int N, int K)
{
    extern __shared__ char smc[];
    const uint32_t smb = (uint32_t)__cvta_generic_to_shared(smc);
    const int tid = threadIdx.x, lane = tid & 31, wid = tid >> 5;
    const int wm = wid & 3, wn = wid >> 2;
    const int m0 = blockIdx.y * 128, n0 = blockIdx.x * 128;
    const int nk = K >> 5;

    // staging: each thread loads half an A row + half a B row (2+2 CP16)
    const int arow = tid >> 1;
    const int ahalf = tid & 1;
    const char* aSrc = (const char*)(Ag + (size_t)(m0 + arow) * K) + ahalf * 32;
    const uint32_t aDst = smb + arow * 80 + ahalf * 32;
    const char* bSrc = (const char*)(Bg + (size_t)(n0 + arow) * K) + ahalf * 32;
    const uint32_t bDst = smb + G1_B + arow * 80 + ahalf * 32;

    #define G1_LOAD(s, kt) do { \
        const char* a_ = aSrc + (size_t)(kt) * 64; \
        const char* b_ = bSrc + (size_t)(kt) * 64; \
        uint32_t ad_ = aDst + (s) * G1_STAGE, bd_ = bDst + (s) * G1_STAGE; \
        CP16(ad_, a_);  CP16(ad_ + 16, a_ + 16); \
        CP16(bd_, b_);  CP16(bd_ + 16, b_ + 16); \
    } while (0)

    float acc[2][8][4];
    #pragma unroll
    for (int i = 0; i < 2; i++)
        #pragma unroll
        for (int j = 0; j < 8; j++)
            #pragma unroll
            for (int k = 0; k < 4; k++) acc[i][j][k] = 0.0f;

    const int rowA = ((lane >> 3) & 1) * 8 + (lane & 7);
    const int colA = (lane >> 4) * 16;
    const int rowB = (lane >> 4) * 8 + (lane & 7);
    const int colB = ((lane >> 3) & 1) * 16;

    G1_LOAD(0, 0); CPCOMMIT();
    G1_LOAD(1, 1); CPCOMMIT();

    for (int kt = 0; kt < nk; kt++) {
        CPWAIT1();
        __syncthreads();
        if (kt + 2 < nk) G1_LOAD((kt + 2) % 3, kt + 2);
        CPCOMMIT();
        const uint32_t st = smb + (uint32_t)(kt % 3) * G1_STAGE;

        #pragma unroll
        for (int ks = 0; ks < 2; ks++) {
            uint32_t ah[2][4];
            #pragma unroll
            for (int mt = 0; mt < 2; mt++) {
                uint32_t aa = st + (uint32_t)(wm * 32 + mt * 16 + rowA) * 80 + ks * 32 + colA;
                LDSM4(ah[mt][0], ah[mt][1], ah[mt][2], ah[mt][3], aa);
            }
            uint32_t bf[4][4];
            #pragma unroll
            for (int ntp = 0; ntp < 4; ntp++) {
                uint32_t ba = st + G1_B + (uint32_t)(wn * 64 + ntp * 16 + rowB) * 80 + ks * 32 + colB;
                LDSM4(bf[ntp][0], bf[ntp][1], bf[ntp][2], bf[ntp][3], ba);
            }
            #pragma unroll
            for (int mt = 0; mt < 2; mt++)
                #pragma unroll
                for (int ntp = 0; ntp < 4; ntp++) {
                    mma_f16(acc[mt][2*ntp],   ah[mt][0], ah[mt][1], ah[mt][2], ah[mt][3],
                            bf[ntp][0], bf[ntp][1]);
                    mma_f16(acc[mt][2*ntp+1], ah[mt][0], ah[mt][1], ah[mt][2], ah[mt][3],
                            bf[ntp][2], bf[ntp][3]);
                }
        }
    }

    #pragma unroll
    for (int nt = 0; nt < 8; nt++) {
        int col = n0 + wn * 64 + nt * 8 + (lane & 3) * 2;
        float2 bs = *(const float2*)&bias[col];
        #pragma unroll
        for (int mt = 0; mt < 2; mt++) {
            int r = m0 + wm * 32 + mt * 16 + (lane >> 2);
            float2 v0 = { acc[mt][nt][0] + bs.x, acc[mt][nt][1] + bs.y };
            float2 v1 = { acc[mt][nt][2] + bs.x, acc[mt][nt][3] + bs.y };
            *(float2*)&C[(size_t)r * N + col]       = v0;
            *(float2*)&C[(size_t)(r + 8) * N + col] = v1;
        }
    }
}

// ---------------------------------------------------------------------------
// 2-term fp16 GEMM + bias (out-proj): C = (Ah+Al) @ B^T + bias.
// (round-14 kernel, unchanged)
// ---------------------------------------------------------------------------
#define GS6_STAGE 30720
#define GS6_SMEM  (3*GS6_STAGE)
#define G6_AL 10240
#define G6_B  20480

__global__ __launch_bounds__(256, 2)
void gemm_f16(const __half* __restrict__ Ahg, const __half* __restrict__ Alg,
              const __half* __restrict__ Bhg,
              const float* __restrict__ bias, float* __restrict__ C,
              int M, int N, int K)
{
    extern __shared__ char smc[];
    const uint32_t smb = (uint32_t)__cvta_generic_to_shared(smc);
    const int tid = threadIdx.x, lane = tid & 31, wid = tid >> 5;
    const int wm = wid & 3, wn = wid >> 2;
    const int m0 = blockIdx.y * 128, n0 = blockIdx.x * 128;
    const int nk = K >> 5;

    const int arow = tid & 127;
    const char* aSrc = (const char*)((tid < 128 ? Ahg : Alg) + (size_t)(m0 + arow) * K);
    const uint32_t aDst = smb + (tid < 128 ? 0 : G6_AL) + arow * 80;
    const int brow = tid >> 1;
    const int bhalf = tid & 1;
    const char* bSrc = (const char*)(Bhg + (size_t)(n0 + brow) * K) + bhalf * 32;
    const uint32_t bDst = smb + G6_B + brow * 80 + bhalf * 32;

    #define G6_LOAD(s, kt) do { \
        const char* a_ = aSrc + (size_t)(kt) * 64; \
        const char* b_ = bSrc + (size_t)(kt) * 64; \
        uint32_t ad_ = aDst + (s) * GS6_STAGE, bd_ = bDst + (s) * GS6_STAGE; \
        CP16(ad_,      a_);       CP16(ad_ + 16, a_ + 16); \
        CP16(ad_ + 32, a_ + 32);  CP16(ad_ + 48, a_ + 48); \
        CP16(bd_,      b_);       CP16(bd_ + 16, b_ + 16); \
    } while (0)

    float acc[2][8][4];
    #pragma unroll
    for (int i = 0; i < 2; i++)
        #pragma unroll
        for (int j = 0; j < 8; j++)
            #pragma unroll
            for (int k = 0; k < 4; k++) acc[i][j][k] = 0.0f;

    const int rowA = ((lane >> 3) & 1) * 8 + (lane & 7);
    const int colA = (lane >> 4) * 16;
    const int rowB = (lane >> 4) * 8 + (lane & 7);
    const int colB = ((lane >> 3) & 1) * 16;

    G6_LOAD(0, 0); CPCOMMIT();
    G6_LOAD(1, 1); CPCOMMIT();

    for (int kt = 0; kt < nk; kt++) {
        CPWAIT1();
        __syncthreads();
        if (kt + 2 < nk) G6_LOAD((kt + 2) % 3, kt + 2);
        CPCOMMIT();
        const uint32_t st = smb + (uint32_t)(kt % 3) * GS6_STAGE;

        #pragma unroll
        for (int ks = 0; ks < 2; ks++) {
            uint32_t ah[2][4], al_[2][4];
            #pragma unroll
            for (int mt = 0; mt < 2; mt++) {
                uint32_t aa = st + (uint32_t)(wm * 32 + mt * 16 + rowA) * 80 + ks * 32 + colA;
                LDSM4(ah[mt][0], ah[mt][1], ah[mt][2], ah[mt][3], aa);
                LDSM4(al_[mt][0], al_[mt][1], al_[mt][2], al_[mt][3], aa + G6_AL);
            }
            uint32_t bf[4][4];
            #pragma unroll
            for (int ntp = 0; ntp < 4; ntp++) {
                uint32_t ba = st + G6_B + (uint32_t)(wn * 64 + ntp * 16 + rowB) * 80 + ks * 32 + colB;
                LDSM4(bf[ntp][0], bf[ntp][1], bf[ntp][2], bf[ntp][3], ba);
            }
            #pragma unroll
            for (int mt = 0; mt < 2; mt++)
                #pragma unroll
                for (int ntp = 0; ntp < 4; ntp++) {
                    mma_f16(acc[mt][2*ntp],   ah[mt][0], ah[mt][1], ah[mt][2], ah[mt][3],
                            bf[ntp][0], bf[ntp][1]);
                    mma_f16(acc[mt][2*ntp+1], ah[mt][0], ah[mt][1], ah[mt][2], ah[mt][3],
                            bf[ntp][2], bf[ntp][3]);
                }
            #pragma unroll
            for (int mt = 0; mt < 2; mt++)
                #pragma unroll
                for (int ntp = 0; ntp < 4; ntp++) {
                    mma_f16(acc[mt][2*ntp],   al_[mt][0], al_[mt][1], al_[mt][2], al_[mt][3],
                            bf[ntp][0], bf[ntp][1]);
                    mma_f16(acc[mt][2*ntp+1], al_[mt][0], al_[mt][1], al_[mt][2], al_[mt][3],
                            bf[ntp][2], bf[ntp][3]);
                }
        }
    }

    #pragma unroll
    for (int nt = 0; nt < 8; nt++) {
        int col = n0 + wn * 64 + nt * 8 + (lane & 3) * 2;
        float2 bs = *(const float2*)&bias[col];
        #pragma unroll
        for (int mt = 0; mt < 2; mt++) {
            int r = m0 + wm * 32 + mt * 16 + (lane >> 2);
            float2 v0 = { acc[mt][nt][0] + bs.x, acc[mt][nt][1] + bs.y };
            float2 v1 = { acc[mt][nt][2] + bs.x, acc[mt][nt][3] + bs.y };
            *(float2*)&C[(size_t)r * N + col]       = v0;
            *(float2*)&C[(size_t)(r + 8) * N + col] = v1;
        }
    }
}

// ---------------------------------------------------------------------------
// Flash attention (round-15 version, unchanged / known-good)
// ---------------------------------------------------------------------------
#define FQ     18432
#define FSTAGE 18432
#define FSM    (FQ + 2*FSTAGE)

__global__ __launch_bounds__(256, 2)
void flash_f16(const __half* __restrict__ Qh,
               const __half* __restrict__ Kh, const __half* __restrict__ Vh)
{
    extern __shared__ char smc[];
    const uint32_t smb = (uint32_t)__cvta_generic_to_shared(smc);
    const int tid = threadIdx.x, lane = tid & 31, wid = tid >> 5;
    const int qt = blockIdx.x, h = blockIdx.y, b = blockIdx.z;
    const size_t bh = (size_t)b * NH + h;

    {
        const int qr = tid >> 1;
        const int qhalf = tid & 1;
        const char* gq = (const char*)(Qh + (bh * SEQ + (size_t)qt * 128 + qr) * 64) + qhalf * 64;
        uint32_t sq = smb + qr * 144 + qhalf * 64;
        #pragma unroll
        for (int c = 0; c < 4; c++) CP16(sq + c*16, gq + c*16);
    }
    const int tile = tid >> 7;
    const int krow = (tid & 127) >> 1;
    const int khalf = tid & 1;
    const char* gkv;
    int gstride;
    if (tile == 0) { gkv = (const char*)(Kh + (bh * SEQ + krow) * 64) + khalf * 64; gstride = 8192; }
    else           { gkv = (const char*)(Vh + (bh * 64 + krow) * SEQ) + khalf * 64; gstride = 128; }
    const uint32_t skv = smb + FQ + tile * 9216 + krow * 144 + khalf * 64;
    #pragma unroll
    for (int c = 0; c < 4; c++) CP16(skv + c*16, gkv + c*16);
    CPCOMMIT();

    float s[8][4], o[8][4];
    float m0r = -INFINITY, m1r = -INFINITY, l0r = 0.0f, l1r = 0.0f;
    #pragma unroll
    for (int i = 0; i < 8; i++)
        #pragma unroll
        for (int j = 0; j < 4; j++) o[i][j] = 0.0f;

    const int rowA = ((lane >> 3) & 1) * 8 + (lane & 7);
    const int colA = (lane >> 4) * 16;
    const int rowB = (lane >> 4) * 8 + (lane & 7);
    const int colB = ((lane >> 3) & 1) * 16;

    for (int t = 0; t < SEQ / 64; t++) {
        CPWAIT0();
        __syncthreads();
        if (t < SEQ / 64 - 1) {
            const char* gp = gkv + (size_t)(t + 1) * gstride;
            uint32_t sp = skv + ((t + 1) & 1) * FSTAGE;
            #pragma unroll
            for (int c = 0; c < 4; c++) CP16(sp + c*16, gp + c*16);
        }
        CPCOMMIT();
        const uint32_t kvb = smb + FQ + (t & 1) * FSTAGE;

        #pragma unroll
        for (int i = 0; i < 8; i++)
            #pragma unroll
            for (int j = 0; j < 4; j++) s[i][j] = 0.0f;

        #pragma unroll
        for (int ks = 0; ks < 4; ks++) {
            uint32_t qa = smb + (uint32_t)(wid * 16 + rowA) * 144 + ks * 32 + colA;
            uint32_t qh0, qh1, qh2, qh3;
            LDSM4(qh0, qh1, qh2, qh3, qa);
            #pragma unroll
            for (int ntp = 0; ntp < 4; ntp++) {
                uint32_t ka = kvb + (uint32_t)(ntp * 16 + rowB) * 144 + ks * 32 + colB;
                uint32_t kh0, kh1, kh2, kh3;
                LDSM4(kh0, kh1, kh2, kh3, ka);
                mma_f16(s[2*ntp],   qh0, qh1, qh2, qh3, kh0, kh1);
                mma_f16(s[2*ntp+1], qh0, qh1, qh2, qh3, kh2, kh3);
            }
        }

        float mx0 = -INFINITY, mx1 = -INFINITY;
        #pragma unroll
        for (int nt = 0; nt < 8; nt++) {
            mx0 = fmaxf(mx0, fmaxf(s[nt][0], s[nt][1]));
            mx1 = fmaxf(mx1, fmaxf(s[nt][2], s[nt][3]));
        }
        mx0 = fmaxf(mx0, __shfl_xor_sync(0xffffffffu, mx0, 1));
        mx0 = fmaxf(mx0, __shfl_xor_sync(0xffffffffu, mx0, 2));
        mx1 = fmaxf(mx1, __shfl_xor_sync(0xffffffffu, mx1, 1));
        mx1 = fmaxf(mx1, __shfl_xor_sync(0xffffffffu, mx1, 2));
        float mn0 = fmaxf(m0r, mx0), mn1 = fmaxf(m1r, mx1);
        float a0 = __expf(m0r - mn0), a1 = __expf(m1r - mn1);
        float sum0 = 0.0f, sum1 = 0.0f;
        #pragma unroll
        for (int nt = 0; nt < 8; nt++) {
            s[nt][0] = __expf(s[nt][0] - mn0); sum0 += s[nt][0];
            s[nt][1] = __expf(s[nt][1] - mn0); sum0 += s[nt][1];
            s[nt][2] = __expf(s[nt][2] - mn1); sum1 += s[nt][2];
            s[nt][3] = __expf(s[nt][3] - mn1); sum1 += s[nt][3];
        }
        sum0 += __shfl_xor_sync(0xffffffffu, sum0, 1);
        sum0 += __shfl_xor_sync(0xffffffffu, sum0, 2);
        sum1 += __shfl_xor_sync(0xffffffffu, sum1, 1);
        sum1 += __shfl_xor_sync(0xffffffffu, sum1, 2);
        l0r = l0r * a0 + sum0;  l1r = l1r * a1 + sum1;
        m0r = mn0;              m1r = mn1;
        #pragma unroll
        for (int dt = 0; dt < 8; dt++) {
            o[dt][0] *= a0; o[dt][1] *= a0;
            o[dt][2] *= a1; o[dt][3] *= a1;
        }

        #pragma unroll
        for (int kt = 0; kt < 4; kt++) {
            uint32_t ah0, ah1, ah2, ah3, au0, au1, au2, au3;
            split_pack2h(s[2*kt][0],   s[2*kt][1],   ah0, au0);
            split_pack2h(s[2*kt][2],   s[2*kt][3],   ah1, au1);
            split_pack2h(s[2*kt+1][0], s[2*kt+1][1], ah2, au2);
            split_pack2h(s[2*kt+1][2], s[2*kt+1][3], ah3, au3);
            #pragma unroll
            for (int dtp = 0; dtp < 4; dtp++) {
                uint32_t va = kvb + 9216 + (uint32_t)(dtp * 16 + rowB) * 144 + kt * 32 + colB;
                uint32_t vh0, vh1, vh2, vh3;
                LDSM4(vh0, vh1, vh2, vh3, va);
                mma_f16(o[2*dtp],   ah0, ah1, ah2, ah3, vh0, vh1);
                mma_f16(o[2*dtp+1], ah0, ah1, ah2, ah3, vh2, vh3);
                mma_f16(o[2*dtp],   au0, au1, au2, au3, vh0, vh1);
                mma_f16(o[2*dtp+1], au0, au1, au2, au3, vh2, vh3);
            }
        }
    }

    float inv0 = 1.0f / l0r, inv1 = 1.0f / l1r;
    const size_t row = (size_t)b * SEQ + (size_t)qt * 128 + wid * 16 + (lane >> 2);
    uint32_t* oh32 = (uint32_t*)g_ath;
    uint32_t* ol32 = (uint32_t*)g_atl;
    #pragma unroll
    for (int dt = 0; dt < 8; dt++) {
        int cp = h * 32 + dt * 4 + (lane & 3);
        uint32_t hh, ll;
        split_pack2h(o[dt][0] * inv0, o[dt][1] * inv0, hh, ll);
        oh32[row * 512 + cp] = hh;       ol32[row * 512 + cp] = ll;
        split_pack2h(o[dt][2] * inv1, o[dt][3] * inv1, hh, ll);
        oh32[(row + 8) * 512 + cp] = hh; ol32[(row + 8) * 512 + cp] = ll;
    }
}

// ---------------------------------------------------------------------------
// Launcher
// ---------------------------------------------------------------------------
extern "C" void kernel_launch(void* const* d_in, const int* in_sizes, int n_in,
                              void* d_out, int out_size)
{
    const float* x     = (const float*)d_in[0];
    const float* w_qkv = (const float*)d_in[1];
    const float* b_qkv = (const float*)d_in[2];
    const float* w_out = (const float*)d_in[3];
    const float* b_out = (const float*)d_in[4];
    float* out = (float*)d_out;

    float* qkvp;
    __half *xh, *wqh, *woh, *Qh, *Kh, *Vh, *ath, *atl;
    cudaGetSymbolAddress((void**)&qkvp, g_qkv);
    cudaGetSymbolAddress((void**)&xh, g_xh);
    cudaGetSymbolAddress((void**)&wqh, g_wqh);
    cudaGetSymbolAddress((void**)&woh, g_woh);
    cudaGetSymbolAddress((void**)&Qh, g_Qh);
    cudaGetSymbolAddress((void**)&Kh, g_Kh);
    cudaGetSymbolAddress((void**)&Vh, g_Vh);
    cudaGetSymbolAddress((void**)&ath, g_ath); cudaGetSymbolAddress((void**)&atl, g_atl);

    cudaFuncSetAttribute(gemm_f16_1t, cudaFuncAttributeMaxDynamicSharedMemorySize, G1_SMEM);
    cudaFuncSetAttribute(gemm_f16,    cudaFuncAttributeMaxDynamicSharedMemorySize, GS6_SMEM);
    cudaFuncSetAttribute(flash_f16,   cudaFuncAttributeMaxDynamicSharedMemorySize, FSM);

    prep_wT<<<dim3(L3 / 32, DM / 32), 256>>>(w_qkv, wqh, DM, L3);
    prep_wT<<<dim3(DM / 32, DM / 32), 256>>>(w_out, woh, DM, DM);
    prep_x<<<(int)(((size_t)ROWS * DM / 2) / 256), 256>>>(x, xh);

    // QKV projection (1-term fp16)
    gemm_f16_1t<<<dim3(L3 / 128, ROWS / 128), 256, G1_SMEM>>>(xh, wqh, b_qkv, qkvp,
                                                              ROWS, L3, DM);
    // RoPE + fp16 conversion
    prep_qkv<<<dim3(SEQ / 64, NH, BATCH), 256>>>(qkvp);

    // flash attention
    flash_f16<<<dim3(SEQ / 128, NH, BATCH), 256, FSM>>>(Qh, Kh, Vh);

    // output projection (2-term: attention output split preserved)
    gemm_f16<<<dim3(DM / 128, ROWS / 128), 256, GS6_SMEM>>>(ath, atl, woh, b_out, out,
                                                            ROWS, DM, DM);
}

// round 17
// speedup vs baseline: 2.3398x; 1.1697x over previous
#include <cuda_runtime.h>
#include <cuda_fp16.h>
#include <math.h>
#include <stdint.h>

#define BATCH 2
#define SEQ   4096
#define DM    1024
#define NH    16
#define DH    64
#define L3    3072
#define ROWS  (BATCH*SEQ)

// ---------------- device scratch (allocation-free) ----------------
__device__ float g_qkv[(size_t)ROWS * L3];
__device__ __half g_xh[(size_t)ROWS*DM];
__device__ __half g_wqh[(size_t)DM*L3];
__device__ __half g_woh[(size_t)DM*DM];
__device__ __half g_Qh[(size_t)ROWS*DM];           // Q single fp16, pre-scaled 1/8
__device__ __half g_Kh[(size_t)ROWS*DM];           // K single fp16
__device__ __half g_Vh[(size_t)ROWS*DM];           // V single fp16, [b][h][d][SEQ]
__device__ __half g_ath[(size_t)ROWS*DM], g_atl[(size_t)ROWS*DM];

// ---------------- helpers ----------------
__device__ __forceinline__ uint32_t pack2h(__half a, __half b) {
    __half2 t; t.x = a; t.y = b;
    return *reinterpret_cast<uint32_t*>(&t);
}
__device__ __forceinline__ void split1h(float f, __half& h, __half& l) {
    h = __float2half_rn(f);
    l = __float2half_rn(f - __half2float(h));
}
__device__ __forceinline__ void split_pack2h(float f0, float f1, uint32_t& h, uint32_t& l) {
    __half h0, l0, h1, l1;
    split1h(f0, h0, l0); split1h(f1, h1, l1);
    h = pack2h(h0, h1); l = pack2h(l0, l1);
}
__device__ __forceinline__ uint32_t pack2f(float f0, float f1) {
    return pack2h(__float2half_rn(f0), __float2half_rn(f1));
}
__device__ __forceinline__ void mma_f16(float c[4],
                                        uint32_t a0, uint32_t a1, uint32_t a2, uint32_t a3,
                                        uint32_t b0, uint32_t b1) {
    asm volatile(
        "mma.sync.aligned.m16n8k16.row.col.f32.f16.f16.f32 "
        "{%0,%1,%2,%3}, {%4,%5,%6,%7}, {%8,%9}, {%0,%1,%2,%3};\n"
        : "+f"(c[0]), "+f"(c[1]), "+f"(c[2]), "+f"(c[3])
        : "r"(a0), "r"(a1), "r"(a2), "r"(a3), "r"(b0), "r"(b1));
}
#define LDSM4(r0,r1,r2,r3,addr) \
    asm volatile("ldmatrix.sync.aligned.m8n8.x4.shared.b16 {%0,%1,%2,%3}, [%4];" \
                 : "=r"(r0),"=r"(r1),"=r"(r2),"=r"(r3) : "r"(addr))
#define CP16(s,g)  asm volatile("cp.async.cg.shared.global [%0], [%1], 16;" :: "r"(s), "l"(g))
#define CPCOMMIT() asm volatile("cp.async.commit_group;" ::: "memory")
#define CPWAIT1()  asm volatile("cp.async.wait_group 1;" ::: "memory")
#define CPWAIT0()  asm volatile("cp.async.wait_group 0;" ::: "memory")

// ---------------- prep kernels ----------------
__global__ void prep_wT(const float* __restrict__ W, __half* __restrict__ WTh,
                        int K, int N)
{
    __shared__ float t[32][33];
    const int tid = threadIdx.x;
    const int n0 = blockIdx.x * 32, k0 = blockIdx.y * 32;
    #pragma unroll
    for (int i = 0; i < 4; i++) {
        int idx = i * 256 + tid;
        t[idx >> 5][idx & 31] = W[(size_t)(k0 + (idx >> 5)) * N + n0 + (idx & 31)];
    }
    __syncthreads();
    uint32_t* oh = (uint32_t*)WTh;
    #pragma unroll
    for (int i = 0; i < 2; i++) {
        int idx = i * 256 + tid;
        int n = idx >> 4, kp = idx & 15;
        oh[((size_t)(n0 + n) * K + k0) / 2 + kp] = pack2f(t[2*kp][n], t[2*kp+1][n]);
    }
}

__global__ void prep_x(const float* __restrict__ x, __half* __restrict__ xh)
{
    size_t i = (size_t)blockIdx.x * 256 + threadIdx.x;
    float2 v = ((const float2*)x)[i];
    ((uint32_t*)xh)[i] = pack2f(v.x, v.y);
}

__global__ void prep_qkv(const float* __restrict__ qkv)
{
    __shared__ float vs[64][65];
    const int tid = threadIdx.x;
    const int lt = blockIdx.x, h = blockIdx.y, b = blockIdx.z;
    const size_t rowg = (size_t)b * SEQ + lt * 64;
    const size_t bh = (size_t)b * NH + h;

    uint32_t* Qh32 = (uint32_t*)g_Qh;
    uint32_t* Kh32 = (uint32_t*)g_Kh;
    uint32_t* Vh32 = (uint32_t*)g_Vh;

    const float nl = -0.194206455f;   // -ln(500)/32
    #pragma unroll
    for (int i = 0; i < 4; i++) {
        int idx = i * 256 + tid;
        int r = idx >> 4, j = idx & 15;
        int l = lt * 64 + r;
        const float* row = qkv + (rowg + r) * L3;
        float f0 = expf((float)(2*j)     * nl);
        float f1 = expf((float)(2*j + 1) * nl);
        float s0, c0, s1, c1;
        sincosf((float)l * f0, &s0, &c0);
        sincosf((float)l * f1, &s1, &c1);
        size_t ob = (bh * SEQ + l) * 32;
        {
            const float* q = row + h * 64;
            float t1a = q[2*j], t1b = q[2*j+1], t2a = q[2*j+32], t2b = q[2*j+33];
            Qh32[ob + j]      = pack2f((t1a*c0 - t2a*s0) * 0.125f, (t1b*c1 - t2b*s1) * 0.125f);
            Qh32[ob + 16 + j] = pack2f((t1a*s0 + t2a*c0) * 0.125f, (t1b*s1 + t2b*c1) * 0.125f);
        }
        {
            const float* k = row + 1024 + h * 64;
            float t1a = k[2*j], t1b = k[2*j+1], t2a = k[2*j+32], t2b = k[2*j+33];
            Kh32[ob + j]      = pack2f(t1a*c0 - t2a*s0, t1b*c1 - t2b*s1);
            Kh32[ob + 16 + j] = pack2f(t1a*s0 + t2a*c0, t1b*s1 + t2b*c1);
        }
    }
    #pragma unroll
    for (int i = 0; i < 4; i++) {
        int idx = i * 256 + tid;
        int r = idx >> 4, c4 = (idx & 15) * 4;
        float4 v = *(const float4*)(qkv + (rowg + r) * L3 + 2048 + h * 64 + c4);
        vs[r][c4] = v.x; vs[r][c4+1] = v.y; vs[r][c4+2] = v.z; vs[r][c4+3] = v.w;
    }
    __syncthreads();
    #pragma unroll
    for (int i = 0; i < 8; i++) {
        int idx = i * 256 + tid;
        int d = idx >> 5, lp = idx & 31;
        Vh32[(bh * 64 + d) * (SEQ/2) + lt * 32 + lp] = pack2f(vs[2*lp][d], vs[2*lp+1][d]);
    }
}

// ---------------------------------------------------------------------------
// 1-term fp16 GEMM + bias (QKV, round-16 version unchanged)
// ---------------------------------------------------------------------------
#define G1_STAGE 20480
#define G1_SMEM  (3*G1_STAGE)
#define G1_B     10240

__global__ __launch_bounds__(256, 2)
void gemm_f16_1t(const __half* __restrict__ Ag, const __half* __restrict__ Bg,
                 const float* __restrict__ bias, float* __restrict__ C,
                 int M, int N, int K)
{
    extern __shared__ char smc[];
    const uint32_t smb = (uint32_t)__cvta_generic_to_shared(smc);
    const int tid = threadIdx.x, lane = tid & 31, wid = tid >> 5;
    const int wm = wid & 3, wn = wid >> 2;
    const int m0 = blockIdx.y * 128, n0 = blockIdx.x * 128;
    const int nk = K >> 5;

    const int arow = tid >> 1;
    const int ahalf = tid & 1;
    const char* aSrc = (const char*)(Ag + (size_t)(m0 + arow) * K) + ahalf * 32;
    const uint32_t aDst = smb + arow * 80 + ahalf * 32;
    const char* bSrc = (const char*)(Bg + (size_t)(n0 + arow) * K) + ahalf * 32;
    const uint32_t bDst = smb + G1_B + arow * 80 + ahalf * 32;

    #define G1_LOAD(s, kt) do { \
        const char* a_ = aSrc + (size_t)(kt) * 64; \
        const char* b_ = bSrc + (size_t)(kt) * 64; \
        uint32_t ad_ = aDst + (s) * G1_STAGE, bd_ = bDst + (s) * G1_STAGE; \
        CP16(ad_, a_);  CP16(ad_ + 16, a_ + 16); \
        CP16(bd_, b_);  CP16(bd_ + 16, b_ + 16); \
    } while (0)

    float acc[2][8][4];
    #pragma unroll
    for (int i = 0; i < 2; i++)
        #pragma unroll
        for (int j = 0; j < 8; j++)
            #pragma unroll
            for (int k = 0; k < 4; k++) acc[i][j][k] = 0.0f;

    const int rowA = ((lane >> 3) & 1) * 8 + (lane & 7);
    const int colA = (lane >> 4) * 16;
    const int rowB = (lane >> 4) * 8 + (lane & 7);
    const int colB = ((lane >> 3) & 1) * 16;

    G1_LOAD(0, 0); CPCOMMIT();
    G1_LOAD(1, 1); CPCOMMIT();

    for (int kt = 0; kt < nk; kt++) {
        CPWAIT1();
        __syncthreads();
        if (kt + 2 < nk) G1_LOAD((kt + 2) % 3, kt + 2);
        CPCOMMIT();
        const uint32_t st = smb + (uint32_t)(kt % 3) * G1_STAGE;

        #pragma unroll
        for (int ks = 0; ks < 2; ks++) {
            uint32_t ah[2][4];
            #pragma unroll
            for (int mt = 0; mt < 2; mt++) {
                uint32_t aa = st + (uint32_t)(wm * 32 + mt * 16 + rowA) * 80 + ks * 32 + colA;
                LDSM4(ah[mt][0], ah[mt][1], ah[mt][2], ah[mt][3], aa);
            }
            uint32_t bf[4][4];
            #pragma unroll
            for (int ntp = 0; ntp < 4; ntp++) {
                uint32_t ba = st + G1_B + (uint32_t)(wn * 64 + ntp * 16 + rowB) * 80 + ks * 32 + colB;
                LDSM4(bf[ntp][0], bf[ntp][1], bf[ntp][2], bf[ntp][3], ba);
            }
            #pragma unroll
            for (int mt = 0; mt < 2; mt++)
                #pragma unroll
                for (int ntp = 0; ntp < 4; ntp++) {
                    mma_f16(acc[mt][2*ntp],   ah[mt][0], ah[mt][1], ah[mt][2], ah[mt][3],
                            bf[ntp][0], bf[ntp][1]);
                    mma_f16(acc[mt][2*ntp+1], ah[mt][0], ah[mt][1], ah[mt][2], ah[mt][3],
                            bf[ntp][2], bf[ntp][3]);
                }
        }
    }

    #pragma unroll
    for (int nt = 0; nt < 8; nt++) {
        int col = n0 + wn * 64 + nt * 8 + (lane & 3) * 2;
        float2 bs = *(const float2*)&bias[col];
        #pragma unroll
        for (int mt = 0; mt < 2; mt++) {
            int r = m0 + wm * 32 + mt * 16 + (lane >> 2);
            float2 v0 = { acc[mt][nt][0] + bs.x, acc[mt][nt][1] + bs.y };
            float2 v1 = { acc[mt][nt][2] + bs.x, acc[mt][nt][3] + bs.y };
            *(float2*)&C[(size_t)r * N + col]       = v0;
            *(float2*)&C[(size_t)(r + 8) * N + col] = v1;
        }
    }
}

// ---------------------------------------------------------------------------
// 2-term fp16 GEMM + bias (out-proj, round-14 version unchanged)
// ---------------------------------------------------------------------------
#define GS6_STAGE 30720
#define GS6_SMEM  (3*GS6_STAGE)
#define G6_AL 10240
#define G6_B  20480

__global__ __launch_bounds__(256, 2)
void gemm_f16(const __half* __restrict__ Ahg, const __half* __restrict__ Alg,
              const __half* __restrict__ Bhg,
              const float* __restrict__ bias, float* __restrict__ C,
              int M, int N, int K)
{
    extern __shared__ char smc[];
    const uint32_t smb = (uint32_t)__cvta_generic_to_shared(smc);
    const int tid = threadIdx.x, lane = tid & 31, wid = tid >> 5;
    const int wm = wid & 3, wn = wid >> 2;
    const int m0 = blockIdx.y * 128, n0 = blockIdx.x * 128;
    const int nk = K >> 5;

    const int arow = tid & 127;
    const char* aSrc = (const char*)((tid < 128 ? Ahg : Alg) + (size_t)(m0 + arow) * K);
    const uint32_t aDst = smb + (tid < 128 ? 0 : G6_AL) + arow * 80;
    const int brow = tid >> 1;
    const int bhalf = tid & 1;
    const char* bSrc = (const char*)(Bhg + (size_t)(n0 + brow) * K) + bhalf * 32;
    const uint32_t bDst = smb + G6_B + brow * 80 + bhalf * 32;

    #define G6_LOAD(s, kt) do { \
        const char* a_ = aSrc + (size_t)(kt) * 64; \
        const char* b_ = bSrc + (size_t)(kt) * 64; \
        uint32_t ad_ = aDst + (s) * GS6_STAGE, bd_ = bDst + (s) * GS6_STAGE; \
        CP16(ad_,      a_);       CP16(ad_ + 16, a_ + 16); \
        CP16(ad_ + 32, a_ + 32);  CP16(ad_ + 48, a_ + 48); \
        CP16(bd_,      b_);       CP16(bd_ + 16, b_ + 16); \
    } while (0)

    float acc[2][8][4];
    #pragma unroll
    for (int i = 0; i < 2; i++)
        #pragma unroll
        for (int j = 0; j < 8; j++)
            #pragma unroll
            for (int k = 0; k < 4; k++) acc[i][j][k] = 0.0f;

    const int rowA = ((lane >> 3) & 1) * 8 + (lane & 7);
    const int colA = (lane >> 4) * 16;
    const int rowB = (lane >> 4) * 8 + (lane & 7);
    const int colB = ((lane >> 3) & 1) * 16;

    G6_LOAD(0, 0); CPCOMMIT();
    G6_LOAD(1, 1); CPCOMMIT();

    for (int kt = 0; kt < nk; kt++) {
        CPWAIT1();
        __syncthreads();
        if (kt + 2 < nk) G6_LOAD((kt + 2) % 3, kt + 2);
        CPCOMMIT();
        const uint32_t st = smb + (uint32_t)(kt % 3) * GS6_STAGE;

        #pragma unroll
        for (int ks = 0; ks < 2; ks++) {
            uint32_t ah[2][4], al_[2][4];
            #pragma unroll
            for (int mt = 0; mt < 2; mt++) {
                uint32_t aa = st + (uint32_t)(wm * 32 + mt * 16 + rowA) * 80 + ks * 32 + colA;
                LDSM4(ah[mt][0], ah[mt][1], ah[mt][2], ah[mt][3], aa);
                LDSM4(al_[mt][0], al_[mt][1], al_[mt][2], al_[mt][3], aa + G6_AL);
            }
            uint32_t bf[4][4];
            #pragma unroll
            for (int ntp = 0; ntp < 4; ntp++) {
                uint32_t ba = st + G6_B + (uint32_t)(wn * 64 + ntp * 16 + rowB) * 80 + ks * 32 + colB;
                LDSM4(bf[ntp][0], bf[ntp][1], bf[ntp][2], bf[ntp][3], ba);
            }
            #pragma unroll
            for (int mt = 0; mt < 2; mt++)
                #pragma unroll
                for (int ntp = 0; ntp < 4; ntp++) {
                    mma_f16(acc[mt][2*ntp],   ah[mt][0], ah[mt][1], ah[mt][2], ah[mt][3],
                            bf[ntp][0], bf[ntp][1]);
                    mma_f16(acc[mt][2*ntp+1], ah[mt][0], ah[mt][1], ah[mt][2], ah[mt][3],
                            bf[ntp][2], bf[ntp][3]);
                }
            #pragma unroll
            for (int mt = 0; mt < 2; mt++)
                #pragma unroll
                for (int ntp = 0; ntp < 4; ntp++) {
                    mma_f16(acc[mt][2*ntp],   al_[mt][0], al_[mt][1], al_[mt][2], al_[mt][3],
                            bf[ntp][0], bf[ntp][1]);
                    mma_f16(acc[mt][2*ntp+1], al_[mt][0], al_[mt][1], al_[mt][2], al_[mt][3],
                            bf[ntp][2], bf[ntp][3]);
                }
        }
    }

    #pragma unroll
    for (int nt = 0; nt < 8; nt++) {
        int col = n0 + wn * 64 + nt * 8 + (lane & 3) * 2;
        float2 bs = *(const float2*)&bias[col];
        #pragma unroll
        for (int mt = 0; mt < 2; mt++) {
            int r = m0 + wm * 32 + mt * 16 + (lane >> 2);
            float2 v0 = { acc[mt][nt][0] + bs.x, acc[mt][nt][1] + bs.y };
            float2 v1 = { acc[mt][nt][2] + bs.x, acc[mt][nt][3] + bs.y };
            *(float2*)&C[(size_t)r * N + col]       = v0;
            *(float2*)&C[(size_t)(r + 8) * N + col] = v1;
        }
    }
}

// ---------------------------------------------------------------------------
// Flash attention: S = Qh·Kh^T (32 MMAs/iter), O += P·Vh SINGLE-TERM
// (32 MMAs/iter; was 64).  64 MMAs/iter total.
// ---------------------------------------------------------------------------
#define FQ     18432
#define FSTAGE 18432
#define FSM    (FQ + 2*FSTAGE)

__global__ __launch_bounds__(256, 2)
void flash_f16(const __half* __restrict__ Qh,
               const __half* __restrict__ Kh, const __half* __restrict__ Vh)
{
    extern __shared__ char smc[];
    const uint32_t smb = (uint32_t)__cvta_generic_to_shared(smc);
    const int tid = threadIdx.x, lane = tid & 31, wid = tid >> 5;
    const int qt = blockIdx.x, h = blockIdx.y, b = blockIdx.z;
    const size_t bh = (size_t)b * NH + h;

    {
        const int qr = tid >> 1;
        const int qhalf = tid & 1;
        const char* gq = (const char*)(Qh + (bh * SEQ + (size_t)qt * 128 + qr) * 64) + qhalf * 64;
        uint32_t sq = smb + qr * 144 + qhalf * 64;
        #pragma unroll
        for (int c = 0; c < 4; c++) CP16(sq + c*16, gq + c*16);
    }
    const int tile = tid >> 7;
    const int krow = (tid & 127) >> 1;
    const int khalf = tid & 1;
    const char* gkv;
    int gstride;
    if (tile == 0) { gkv = (const char*)(Kh + (bh * SEQ + krow) * 64) + khalf * 64; gstride = 8192; }
    else           { gkv = (const char*)(Vh + (bh * 64 + krow) * SEQ) + khalf * 64; gstride = 128; }
    const uint32_t skv = smb + FQ + tile * 9216 + krow * 144 + khalf * 64;
    #pragma unroll
    for (int c = 0; c < 4; c++) CP16(skv + c*16, gkv + c*16);
    CPCOMMIT();

    float s[8][4], o[8][4];
    float m0r = -INFINITY, m1r = -INFINITY, l0r = 0.0f, l1r = 0.0f;
    #pragma unroll
    for (int i = 0; i < 8; i++)
        #pragma unroll
        for (int j = 0; j < 4; j++) o[i][j] = 0.0f;

    const int rowA = ((lane >> 3) & 1) * 8 + (lane & 7);
    const int colA = (lane >> 4) * 16;
    const int rowB = (lane >> 4) * 8 + (lane & 7);
    const int colB = ((lane >> 3) & 1) * 16;

    for (int t = 0; t < SEQ / 64; t++) {
        CPWAIT0();
        __syncthreads();
        if (t < SEQ / 64 - 1) {
            const char* gp = gkv + (size_t)(t + 1) * gstride;
            uint32_t sp = skv + ((t + 1) & 1) * FSTAGE;
            #pragma unroll
            for (int c = 0; c < 4; c++) CP16(sp + c*16, gp + c*16);
        }
        CPCOMMIT();
        const uint32_t kvb = smb + FQ + (t & 1) * FSTAGE;

        #pragma unroll
        for (int i = 0; i < 8; i++)
            #pragma unroll
            for (int j = 0; j < 4; j++) s[i][j] = 0.0f;

        // ---- S = Qh @ Kh^T
        #pragma unroll
        for (int ks = 0; ks < 4; ks++) {
            uint32_t qa = smb + (uint32_t)(wid * 16 + rowA) * 144 + ks * 32 + colA;
            uint32_t qh0, qh1, qh2, qh3;
            LDSM4(qh0, qh1, qh2, qh3, qa);
            #pragma unroll
            for (int ntp = 0; ntp < 4; ntp++) {
                uint32_t ka = kvb + (uint32_t)(ntp * 16 + rowB) * 144 + ks * 32 + colB;
                uint32_t kh0, kh1, kh2, kh3;
                LDSM4(kh0, kh1, kh2, kh3, ka);
                mma_f16(s[2*ntp],   qh0, qh1, qh2, qh3, kh0, kh1);
                mma_f16(s[2*ntp+1], qh0, qh1, qh2, qh3, kh2, kh3);
            }
        }

        // ---- online softmax
        float mx0 = -INFINITY, mx1 = -INFINITY;
        #pragma unroll
        for (int nt = 0; nt < 8; nt++) {
            mx0 = fmaxf(mx0, fmaxf(s[nt][0], s[nt][1]));
            mx1 = fmaxf(mx1, fmaxf(s[nt][2], s[nt][3]));
        }
        mx0 = fmaxf(mx0, __shfl_xor_sync(0xffffffffu, mx0, 1));
        mx0 = fmaxf(mx0, __shfl_xor_sync(0xffffffffu, mx0, 2));
        mx1 = fmaxf(mx1, __shfl_xor_sync(0xffffffffu, mx1, 1));
        mx1 = fmaxf(mx1, __shfl_xor_sync(0xffffffffu, mx1, 2));
        float mn0 = fmaxf(m0r, mx0), mn1 = fmaxf(m1r, mx1);
        float a0 = __expf(m0r - mn0), a1 = __expf(m1r - mn1);
        float sum0 = 0.0f, sum1 = 0.0f;
        #pragma unroll
        for (int nt = 0; nt < 8; nt++) {
            s[nt][0] = __expf(s[nt][0] - mn0); sum0 += s[nt][0];
            s[nt][1] = __expf(s[nt][1] - mn0); sum0 += s[nt][1];
            s[nt][2] = __expf(s[nt][2] - mn1); sum1 += s[nt][2];
            s[nt][3] = __expf(s[nt][3] - mn1); sum1 += s[nt][3];
        }
        sum0 += __shfl_xor_sync(0xffffffffu, sum0, 1);
        sum0 += __shfl_xor_sync(0xffffffffu, sum0, 2);
        sum1 += __shfl_xor_sync(0xffffffffu, sum1, 1);
        sum1 += __shfl_xor_sync(0xffffffffu, sum1, 2);
        l0r = l0r * a0 + sum0;  l1r = l1r * a1 + sum1;
        m0r = mn0;              m1r = mn1;
        #pragma unroll
        for (int dt = 0; dt < 8; dt++) {
            o[dt][0] *= a0; o[dt][1] *= a0;
            o[dt][2] *= a1; o[dt][3] *= a1;
        }

        // ---- O += P @ Vh (single-term fp16 P)
        #pragma unroll
        for (int kt = 0; kt < 4; kt++) {
            uint32_t ah0 = pack2f(s[2*kt][0],   s[2*kt][1]);
            uint32_t ah1 = pack2f(s[2*kt][2],   s[2*kt][3]);
            uint32_t ah2 = pack2f(s[2*kt+1][0], s[2*kt+1][1]);
            uint32_t ah3 = pack2f(s[2*kt+1][2], s[2*kt+1][3]);
            #pragma unroll
            for (int dtp = 0; dtp < 4; dtp++) {
                uint32_t va = kvb + 9216 + (uint32_t)(dtp * 16 + rowB) * 144 + kt * 32 + colB;
                uint32_t vh0, vh1, vh2, vh3;
                LDSM4(vh0, vh1, vh2, vh3, va);
                mma_f16(o[2*dtp],   ah0, ah1, ah2, ah3, vh0, vh1);
                mma_f16(o[2*dtp+1], ah0, ah1, ah2, ah3, vh2, vh3);
            }
        }
    }

    float inv0 = 1.0f / l0r, inv1 = 1.0f / l1r;
    const size_t row = (size_t)b * SEQ + (size_t)qt * 128 + wid * 16 + (lane >> 2);
    uint32_t* oh32 = (uint32_t*)g_ath;
    uint32_t* ol32 = (uint32_t*)g_atl;
    #pragma unroll
    for (int dt = 0; dt < 8; dt++) {
        int cp = h * 32 + dt * 4 + (lane & 3);
        uint32_t hh, ll;
        split_pack2h(o[dt][0] * inv0, o[dt][1] * inv0, hh, ll);
        oh32[row * 512 + cp] = hh;       ol32[row * 512 + cp] = ll;
        split_pack2h(o[dt][2] * inv1, o[dt][3] * inv1, hh, ll);
        oh32[(row + 8) * 512 + cp] = hh; ol32[(row + 8) * 512 + cp] = ll;
    }
}

// ---------------------------------------------------------------------------
// Launcher
// ---------------------------------------------------------------------------
extern "C" void kernel_launch(void* const* d_in, const int* in_sizes, int n_in,
                              void* d_out, int out_size)
{
    const float* x     = (const float*)d_in[0];
    const float* w_qkv = (const float*)d_in[1];
    const float* b_qkv = (const float*)d_in[2];
    const float* w_out = (const float*)d_in[3];
    const float* b_out = (const float*)d_in[4];
    float* out = (float*)d_out;

    float* qkvp;
    __half *xh, *wqh, *woh, *Qh, *Kh, *Vh, *ath, *atl;
    cudaGetSymbolAddress((void**)&qkvp, g_qkv);
    cudaGetSymbolAddress((void**)&xh, g_xh);
    cudaGetSymbolAddress((void**)&wqh, g_wqh);
    cudaGetSymbolAddress((void**)&woh, g_woh);
    cudaGetSymbolAddress((void**)&Qh, g_Qh);
    cudaGetSymbolAddress((void**)&Kh, g_Kh);
    cudaGetSymbolAddress((void**)&Vh, g_Vh);
    cudaGetSymbolAddress((void**)&ath, g_ath); cudaGetSymbolAddress((void**)&atl, g_atl);

    cudaFuncSetAttribute(gemm_f16_1t, cudaFuncAttributeMaxDynamicSharedMemorySize, G1_SMEM);
    cudaFuncSetAttribute(gemm_f16,    cudaFuncAttributeMaxDynamicSharedMemorySize, GS6_SMEM);
    cudaFuncSetAttribute(flash_f16,   cudaFuncAttributeMaxDynamicSharedMemorySize, FSM);

    prep_wT<<<dim3(L3 / 32, DM / 32), 256>>>(w_qkv, wqh, DM, L3);
    prep_wT<<<dim3(DM / 32, DM / 32), 256>>>(w_out, woh, DM, DM);
    prep_x<<<(int)(((size_t)ROWS * DM / 2) / 256), 256>>>(x, xh);

    // QKV projection (1-term fp16)
    gemm_f16_1t<<<dim3(L3 / 128, ROWS / 128), 256, G1_SMEM>>>(xh, wqh, b_qkv, qkvp,
                                                              ROWS, L3, DM);
    // RoPE + fp16 conversion
    prep_qkv<<<dim3(SEQ / 64, NH, BATCH), 256>>>(qkvp);

    // flash attention (single-term PV)
    flash_f16<<<dim3(SEQ / 128, NH, BATCH), 256, FSM>>>(Qh, Kh, Vh);

    // output projection (2-term: attention output split preserved)
    gemm_f16<<<dim3(DM / 128, ROWS / 128), 256, GS6_SMEM>>>(ath, atl, woh, b_out, out,
                                                            ROWS, DM, DM);
}